// round 3
// baseline (speedup 1.0000x reference)
#include <cuda_runtime.h>
#include <cstddef>

// Problem dims
#define B_ 4
#define S_ 2048
#define DM_ 512
#define DA_ 512
#define H_ 8
#define F_ 4
#define DEP_ 64
#define BS_ (B_ * S_)   // 8192

// ---------------- scratch (no allocations allowed) ----------------
__device__ float g_qp[(size_t)BS_ * DA_];
__device__ float g_kp[(size_t)BS_ * DA_];
__device__ float g_vp[(size_t)BS_ * DA_];
__device__ float g_xs[(size_t)BS_ * (H_ * F_)];
__device__ float g_ctx[(size_t)BS_ * DA_];

// =================================================================
// SGEMM: C[M,N] = A[M,K] @ W[K,N] + bias[N]
// 128x128 block tile, BK=8, 256 threads, 8x8 per thread.
// =================================================================
__global__ __launch_bounds__(256) void sgemm128(
    const float* __restrict__ A, const float* __restrict__ W,
    const float* __restrict__ bias, float* __restrict__ C,
    int M, int N, int K)
{
    __shared__ float As[8][132];
    __shared__ float Bs[8][128];

    const int tid = threadIdx.x;
    const int m0 = blockIdx.y * 128;
    const int n0 = blockIdx.x * 128;
    const int ty = tid >> 4;       // 0..15
    const int tx = tid & 15;       // 0..15

    const int arow = tid >> 1;           // 0..127
    const int ak   = (tid & 1) * 4;      // 0 or 4
    const int brow = tid >> 5;           // 0..7
    const int bn   = (tid & 31) * 4;     // 0..124

    const float* Aptr = A + (size_t)(m0 + arow) * K + ak;
    const float* Wptr = W + (size_t)brow * N + n0 + bn;

    float acc[8][8];
#pragma unroll
    for (int i = 0; i < 8; i++)
#pragma unroll
        for (int j = 0; j < 8; j++) acc[i][j] = 0.0f;

    for (int k0 = 0; k0 < K; k0 += 8) {
        float4 av = *(const float4*)(Aptr + k0);
        float4 bv = *(const float4*)(Wptr + (size_t)k0 * N);
        As[ak + 0][arow] = av.x;
        As[ak + 1][arow] = av.y;
        As[ak + 2][arow] = av.z;
        As[ak + 3][arow] = av.w;
        *(float4*)&Bs[brow][bn] = bv;
        __syncthreads();

#pragma unroll
        for (int kk = 0; kk < 8; kk++) {
            float4 a0 = *(float4*)&As[kk][ty * 4];
            float4 a1 = *(float4*)&As[kk][64 + ty * 4];
            float4 b0 = *(float4*)&Bs[kk][tx * 4];
            float4 b1 = *(float4*)&Bs[kk][64 + tx * 4];
            float ar[8] = {a0.x, a0.y, a0.z, a0.w, a1.x, a1.y, a1.z, a1.w};
            float br[8] = {b0.x, b0.y, b0.z, b0.w, b1.x, b1.y, b1.z, b1.w};
#pragma unroll
            for (int i = 0; i < 8; i++)
#pragma unroll
                for (int j = 0; j < 8; j++)
                    acc[i][j] += ar[i] * br[j];
        }
        __syncthreads();
    }

    const float4 bias0 = *(const float4*)&bias[n0 + tx * 4];
    const float4 bias1 = *(const float4*)&bias[n0 + 64 + tx * 4];
#pragma unroll
    for (int i = 0; i < 8; i++) {
        int r = m0 + ((i < 4) ? (ty * 4 + i) : (64 + ty * 4 + (i - 4)));
        float4 o0 = {acc[i][0] + bias0.x, acc[i][1] + bias0.y,
                     acc[i][2] + bias0.z, acc[i][3] + bias0.w};
        float4 o1 = {acc[i][4] + bias1.x, acc[i][5] + bias1.y,
                     acc[i][6] + bias1.z, acc[i][7] + bias1.w};
        *(float4*)&C[(size_t)r * N + n0 + tx * 4] = o0;
        *(float4*)&C[(size_t)r * N + n0 + 64 + tx * 4] = o1;
    }
}

// =================================================================
// x projection: xs[8192,32] = qp[8192,512] @ wx[512,32] + bx
// one output per thread; warp shares a row (A broadcast, W coalesced)
// =================================================================
__global__ __launch_bounds__(256) void xproj_kernel(
    const float* __restrict__ qp, const float* __restrict__ wx,
    const float* __restrict__ bx, float* __restrict__ xs)
{
    int idx = blockIdx.x * 256 + threadIdx.x;       // < 8192*32
    int row = idx >> 5;
    int col = idx & 31;
    const float* arow = qp + (size_t)row * DA_;
    float a0 = bx[col], a1 = 0.f, a2 = 0.f, a3 = 0.f;
#pragma unroll 4
    for (int k = 0; k < DA_; k += 4) {
        a0 += arow[k + 0] * wx[(k + 0) * 32 + col];
        a1 += arow[k + 1] * wx[(k + 1) * 32 + col];
        a2 += arow[k + 2] * wx[(k + 2) * 32 + col];
        a3 += arow[k + 3] * wx[(k + 3) * 32 + col];
    }
    xs[idx] = (a0 + a1) + (a2 + a3);
}

// =================================================================
// Logits: attn[b,h,q,k] = (qh.kh)/8 + 0.5 * sum_f xdiff[b,q,k,f]*x[b,q,h,f]
// One block = (b, 64 q-rows, 64 k-cols), loops over all 8 heads so the
// xdiff tile is loaded from HBM exactly once.
// Dynamic smem layout (floats):
//   qt[64][68]  (d-major), kt[64][68] (d-major), xw[64][32], xd float4[64][65]
// =================================================================
#define LOGITS_SMEM (size_t)((64 * 68 + 64 * 68 + 64 * 32) * 4 + 64 * 65 * 16)

__global__ __launch_bounds__(256) void logits_kernel(
    const float* __restrict__ qp, const float* __restrict__ kp,
    const float* __restrict__ xs, const float* __restrict__ xdiff,
    float* __restrict__ attn)
{
    extern __shared__ float sm[];
    float*  qt = sm;                       // 64*68 = 4352
    float*  kt = sm + 4352;                // 4352
    float*  xw = sm + 8704;                // 2048
    float4* xd = (float4*)(sm + 10752);    // [64][65] float4 (16B-aligned)

    const int tid = threadIdx.x;
    const int b  = blockIdx.z;
    const int q0 = blockIdx.y * 64;
    const int k0 = blockIdx.x * 64;

    // --- load xdiff tile [64 q][64 k] as float4 (F=4 contiguous) ---
    {
        const float4* xdg = (const float4*)xdiff;
#pragma unroll
        for (int r = 0; r < 16; r++) {
            int l  = tid + 256 * r;        // 0..4095
            int qi = l >> 6;
            int kj = l & 63;
            xd[qi * 65 + kj] = xdg[((size_t)(b * S_ + q0 + qi)) * S_ + k0 + kj];
        }
    }
    // --- load x tile [64 q][32 hf] ---
    {
#pragma unroll
        for (int r = 0; r < 2; r++) {
            int l   = tid + 256 * r;       // 0..511 (float4 units)
            int qi  = l >> 3;
            int hf4 = (l & 7) * 4;
            *(float4*)&xw[qi * 32 + hf4] =
                *(const float4*)&xs[(size_t)(b * S_ + q0 + qi) * 32 + hf4];
        }
    }
    __syncthreads();

    const int a = tid >> 4;   // q-group 0..15 -> rows a*4..a*4+3
    const int c = tid & 15;   // k-group 0..15 -> cols c*4..c*4+3

    for (int h = 0; h < H_; h++) {
        // load qt/kt for this head, d-major: qt[d][qi]
#pragma unroll
        for (int r = 0; r < 4; r++) {
            int l  = tid + 256 * r;        // 0..1023
            int qi = l >> 4;
            int dg = (l & 15) * 4;
            float4 v = *(const float4*)&qp[(size_t)(b * S_ + q0 + qi) * DA_ + h * DEP_ + dg];
            qt[(dg + 0) * 68 + qi] = v.x;
            qt[(dg + 1) * 68 + qi] = v.y;
            qt[(dg + 2) * 68 + qi] = v.z;
            qt[(dg + 3) * 68 + qi] = v.w;
            float4 w = *(const float4*)&kp[(size_t)(b * S_ + k0 + qi) * DA_ + h * DEP_ + dg];
            kt[(dg + 0) * 68 + qi] = w.x;
            kt[(dg + 1) * 68 + qi] = w.y;
            kt[(dg + 2) * 68 + qi] = w.z;
            kt[(dg + 3) * 68 + qi] = w.w;
        }
        __syncthreads();

        float acc[4][4];
#pragma unroll
        for (int i = 0; i < 4; i++)
#pragma unroll
            for (int j = 0; j < 4; j++) acc[i][j] = 0.0f;

#pragma unroll 8
        for (int d = 0; d < DEP_; d++) {
            float4 qv = *(float4*)&qt[d * 68 + a * 4];
            float4 kv = *(float4*)&kt[d * 68 + c * 4];
            float ar[4] = {qv.x, qv.y, qv.z, qv.w};
            float br[4] = {kv.x, kv.y, kv.z, kv.w};
#pragma unroll
            for (int i = 0; i < 4; i++)
#pragma unroll
                for (int j = 0; j < 4; j++)
                    acc[i][j] += ar[i] * br[j];
        }

        // epilogue: scale + xdiff bias, write float4
#pragma unroll
        for (int i = 0; i < 4; i++) {
            int qi = a * 4 + i;
            float4 xh = *(float4*)&xw[qi * 32 + h * 4];
            float4 o;
            float* op = &o.x;
#pragma unroll
            for (int j = 0; j < 4; j++) {
                float4 xv = xd[qi * 65 + c * 4 + j];
                float bias = xv.x * xh.x + xv.y * xh.y + xv.z * xh.z + xv.w * xh.w;
                op[j] = acc[i][j] * 0.125f + bias * 0.5f;
            }
            *(float4*)&attn[((size_t)((b * H_ + h) * S_ + q0 + qi)) * S_ + k0 + c * 4] = o;
        }
        __syncthreads();
    }
}

// =================================================================
// Softmax over last dim (2048) — one block per row, all in registers
// =================================================================
__global__ __launch_bounds__(256) void softmax_kernel(float* __restrict__ attn)
{
    __shared__ float red[8];
    const size_t row = blockIdx.x;
    float4* p = (float4*)(attn + row * (size_t)S_);
    const int tid = threadIdx.x;

    float4 v0 = p[tid];
    float4 v1 = p[tid + 256];

    float m = fmaxf(fmaxf(fmaxf(v0.x, v0.y), fmaxf(v0.z, v0.w)),
                    fmaxf(fmaxf(v1.x, v1.y), fmaxf(v1.z, v1.w)));
#pragma unroll
    for (int o = 16; o > 0; o >>= 1) m = fmaxf(m, __shfl_xor_sync(0xffffffffu, m, o));
    if ((tid & 31) == 0) red[tid >> 5] = m;
    __syncthreads();
    m = red[0];
#pragma unroll
    for (int i = 1; i < 8; i++) m = fmaxf(m, red[i]);
    __syncthreads();

    v0.x = __expf(v0.x - m); v0.y = __expf(v0.y - m);
    v0.z = __expf(v0.z - m); v0.w = __expf(v0.w - m);
    v1.x = __expf(v1.x - m); v1.y = __expf(v1.y - m);
    v1.z = __expf(v1.z - m); v1.w = __expf(v1.w - m);

    float s = (v0.x + v0.y + v0.z + v0.w) + (v1.x + v1.y + v1.z + v1.w);
#pragma unroll
    for (int o = 16; o > 0; o >>= 1) s += __shfl_xor_sync(0xffffffffu, s, o);
    if ((tid & 31) == 0) red[tid >> 5] = s;
    __syncthreads();
    s = red[0];
#pragma unroll
    for (int i = 1; i < 8; i++) s += red[i];

    float inv = 1.0f / s;
    v0.x *= inv; v0.y *= inv; v0.z *= inv; v0.w *= inv;
    v1.x *= inv; v1.y *= inv; v1.z *= inv; v1.w *= inv;
    p[tid] = v0;
    p[tid + 256] = v1;
}

// =================================================================
// PV: ctx[b, q, h*64+d] = sum_k attn[b,h,q,k] * vp[b,k,h*64+d]
// block = (q-tile of 128, bh); K loop in chunks of 32; 8x4 per thread
// =================================================================
__global__ __launch_bounds__(256) void pv_kernel(
    const float* __restrict__ attn, const float* __restrict__ vp,
    float* __restrict__ ctx)
{
    __shared__ float As[32][136];   // [kk][qi] transposed
    __shared__ float Vs[32][68];    // [kk][dj]

    const int tid = threadIdx.x;
    const int bh = blockIdx.y;
    const int b  = bh >> 3;
    const int h  = bh & 7;
    const int q0 = blockIdx.x * 128;

    const int a = tid >> 4;   // 0..15 -> rows a*8..a*8+7
    const int c = tid & 15;   // 0..15 -> cols c*4..c*4+3

    float acc[8][4];
#pragma unroll
    for (int i = 0; i < 8; i++)
#pragma unroll
        for (int j = 0; j < 4; j++) acc[i][j] = 0.0f;

    for (int k0 = 0; k0 < S_; k0 += 32) {
        // attn tile: 128 q x 32 k
#pragma unroll
        for (int r = 0; r < 4; r++) {
            int l  = tid + 256 * r;      // 0..1023 (float4 units)
            int qi = l >> 3;
            int kg = (l & 7) * 4;
            float4 v = *(const float4*)&attn[((size_t)(bh * S_ + q0 + qi)) * S_ + k0 + kg];
            As[kg + 0][qi] = v.x;
            As[kg + 1][qi] = v.y;
            As[kg + 2][qi] = v.z;
            As[kg + 3][qi] = v.w;
        }
        // v tile: 32 k x 64 d
#pragma unroll
        for (int r = 0; r < 2; r++) {
            int l  = tid + 256 * r;      // 0..511 (float4 units)
            int kk = l >> 4;
            int dg = (l & 15) * 4;
            *(float4*)&Vs[kk][dg] =
                *(const float4*)&vp[(size_t)(b * S_ + k0 + kk) * DA_ + h * DEP_ + dg];
        }
        __syncthreads();

#pragma unroll 8
        for (int kk = 0; kk < 32; kk++) {
            float4 a0 = *(float4*)&As[kk][a * 8];
            float4 a1 = *(float4*)&As[kk][a * 8 + 4];
            float4 bv = *(float4*)&Vs[kk][c * 4];
            float ar[8] = {a0.x, a0.y, a0.z, a0.w, a1.x, a1.y, a1.z, a1.w};
            float br[4] = {bv.x, bv.y, bv.z, bv.w};
#pragma unroll
            for (int i = 0; i < 8; i++)
#pragma unroll
                for (int j = 0; j < 4; j++)
                    acc[i][j] += ar[i] * br[j];
        }
        __syncthreads();
    }

#pragma unroll
    for (int i = 0; i < 8; i++) {
        float4 o = {acc[i][0], acc[i][1], acc[i][2], acc[i][3]};
        *(float4*)&ctx[(size_t)(b * S_ + q0 + a * 8 + i) * DA_ + h * DEP_ + c * 4] = o;
    }
}

// =================================================================
extern "C" void kernel_launch(void* const* d_in, const int* in_sizes, int n_in,
                              void* d_out, int out_size)
{
    const float* q     = (const float*)d_in[0];
    const float* k     = (const float*)d_in[1];
    const float* v     = (const float*)d_in[2];
    const float* xdiff = (const float*)d_in[3];
    const float* wq    = (const float*)d_in[4];
    const float* bq    = (const float*)d_in[5];
    const float* wk    = (const float*)d_in[6];
    const float* bk    = (const float*)d_in[7];
    const float* wv    = (const float*)d_in[8];
    const float* bv    = (const float*)d_in[9];
    const float* wx    = (const float*)d_in[10];
    const float* bx    = (const float*)d_in[11];
    const float* wo    = (const float*)d_in[12];
    const float* bo    = (const float*)d_in[13];

    float* out  = (float*)d_out;                        // [B,S,DM]
    float* attn = out + (size_t)BS_ * DM_;              // [B,H,S,S]

    float *qp, *kp, *vp, *xs, *ctx;
    cudaGetSymbolAddress((void**)&qp,  g_qp);
    cudaGetSymbolAddress((void**)&kp,  g_kp);
    cudaGetSymbolAddress((void**)&vp,  g_vp);
    cudaGetSymbolAddress((void**)&xs,  g_xs);
    cudaGetSymbolAddress((void**)&ctx, g_ctx);

    dim3 gProj(DA_ / 128, BS_ / 128);   // (4, 64)

    // projections
    sgemm128<<<gProj, 256>>>(q, wq, bq, qp, BS_, DA_, DM_);
    sgemm128<<<gProj, 256>>>(k, wk, bk, kp, BS_, DA_, DM_);
    sgemm128<<<gProj, 256>>>(v, wv, bv, vp, BS_, DA_, DM_);

    // x = qp @ wx + bx
    xproj_kernel<<<(BS_ * 32) / 256, 256>>>(qp, wx, bx, xs);

    // logits (+ xdiff bias) -> attn buffer
    cudaFuncSetAttribute(logits_kernel,
                         cudaFuncAttributeMaxDynamicSharedMemorySize,
                         (int)LOGITS_SMEM);
    logits_kernel<<<dim3(S_ / 64, S_ / 64, B_), 256, LOGITS_SMEM>>>(
        qp, kp, xs, xdiff, attn);

    // softmax in place
    softmax_kernel<<<B_ * H_ * S_, 256>>>(attn);

    // attn @ V -> ctx (head-merged layout)
    pv_kernel<<<dim3(S_ / 128, B_ * H_), 256>>>(attn, vp, ctx);

    // out = ctx @ wo + bo
    sgemm128<<<gProj, 256>>>(ctx, wo, bo, out, BS_, DM_, DA_);
}

// round 7
// speedup vs baseline: 1.0424x; 1.0424x over previous
#include <cuda_runtime.h>
#include <mma.h>
#include <cstdint>
#include <cstddef>

using namespace nvcuda;

// Problem dims
#define B_ 4
#define S_ 2048
#define DM_ 512
#define DA_ 512
#define H_ 8
#define F_ 4
#define DEP_ 64
#define BS_ (B_ * S_)   // 8192

// ---------------- scratch (no allocations allowed) ----------------
__device__ float g_qp[(size_t)BS_ * DA_];
__device__ float g_kp[(size_t)BS_ * DA_];
__device__ float g_vp[(size_t)BS_ * DA_];
__device__ float g_xs[(size_t)BS_ * (H_ * F_)];
__device__ float g_ctx[(size_t)BS_ * DA_];

typedef wmma::fragment<wmma::matrix_a, 16, 16, 8, wmma::precision::tf32, wmma::row_major> FragA;
typedef wmma::fragment<wmma::matrix_b, 16, 16, 8, wmma::precision::tf32, wmma::row_major> FragB;
typedef wmma::fragment<wmma::matrix_b, 16, 16, 8, wmma::precision::tf32, wmma::col_major> FragBc;
typedef wmma::fragment<wmma::accumulator, 16, 16, 8, float> FragC;

template <typename F>
__device__ __forceinline__ void cvt_tf32(F& f) {
#pragma unroll
    for (int i = 0; i < f.num_elements; i++)
        f.x[i] = wmma::__float_to_tf32(f.x[i]);
}

// =================================================================
// WMMA tf32 GEMM: C[M,N] = A[M,K] @ W[K,N] + bias[N]
// Block tile 128 x BN, BK=32, 256 threads (8 warps).
// Warp grid WR x WC; warp tile (128/WR) x (BN/WC).
// =================================================================
template <int BN, int WR, int WC>
__global__ __launch_bounds__(256) void gemm_wmma(
    const float* __restrict__ A, const float* __restrict__ W,
    const float* __restrict__ bias, float* __restrict__ C,
    int M, int N, int K)
{
    constexpr int LDA = 36;        // 32 + 4 pad
    constexpr int LDB = BN + 4;
    constexpr int MI = 128 / (WR * 16);
    constexpr int NI = BN / (WC * 16);

    extern __shared__ float sm[];
    float* As = sm;                  // [128][36]
    float* Ws = sm + 128 * LDA;      // [32][BN+4]
    float* Cs = sm;                  // reused for epilogue: [128][BN+4]

    const int tid = threadIdx.x;
    const int wid = tid >> 5;
    const int warp_m = wid % WR;
    const int warp_n = wid / WR;
    const int m0 = blockIdx.y * 128;
    const int n0 = blockIdx.x * BN;

    FragC acc[MI][NI];
#pragma unroll
    for (int i = 0; i < MI; i++)
#pragma unroll
        for (int j = 0; j < NI; j++) wmma::fill_fragment(acc[i][j], 0.0f);

    for (int k0 = 0; k0 < K; k0 += 32) {
        // A tile: 128 x 32 -> 1024 float4, 4 per thread
#pragma unroll
        for (int r = 0; r < 4; r++) {
            int idx = tid + 256 * r;
            int m = idx >> 3, k4 = (idx & 7) * 4;
            *(float4*)&As[m * LDA + k4] =
                *(const float4*)&A[(size_t)(m0 + m) * K + k0 + k4];
        }
        // W tile: 32 x BN
#pragma unroll
        for (int r = 0; r < BN / 32; r++) {
            int idx = tid + 256 * r;
            int kk = idx / (BN / 4), n4 = (idx % (BN / 4)) * 4;
            *(float4*)&Ws[kk * LDB + n4] =
                *(const float4*)&W[(size_t)(k0 + kk) * N + n0 + n4];
        }
        __syncthreads();

#pragma unroll
        for (int ds = 0; ds < 4; ds++) {
            FragA af[MI];
#pragma unroll
            for (int i = 0; i < MI; i++) {
                wmma::load_matrix_sync(af[i],
                    &As[(warp_m * (128 / WR) + i * 16) * LDA + ds * 8], LDA);
                cvt_tf32(af[i]);
            }
            FragB bf;
#pragma unroll
            for (int j = 0; j < NI; j++) {
                wmma::load_matrix_sync(bf,
                    &Ws[ds * 8 * LDB + warp_n * (BN / WC) + j * 16], LDB);
                cvt_tf32(bf);
#pragma unroll
                for (int i = 0; i < MI; i++)
                    wmma::mma_sync(acc[i][j], af[i], bf, acc[i][j]);
            }
        }
        __syncthreads();
    }

    // epilogue: frags -> smem -> (+bias) -> global
#pragma unroll
    for (int i = 0; i < MI; i++)
#pragma unroll
        for (int j = 0; j < NI; j++)
            wmma::store_matrix_sync(
                &Cs[(warp_m * (128 / WR) + i * 16) * LDB +
                    warp_n * (BN / WC) + j * 16],
                acc[i][j], LDB, wmma::mem_row_major);
    __syncthreads();

#pragma unroll
    for (int r = 0; r < BN / 8; r++) {
        int idx = tid + 256 * r;
        int m = idx / (BN / 4), n4 = (idx % (BN / 4)) * 4;
        float4 v = *(float4*)&Cs[m * LDB + n4];
        float4 bz = *(const float4*)&bias[n0 + n4];
        v.x += bz.x; v.y += bz.y; v.z += bz.z; v.w += bz.w;
        *(float4*)&C[(size_t)(m0 + m) * N + n0 + n4] = v;
    }
}

// =================================================================
// Logits: attn[b,h,q,k] = (qh.kh)/8 + 0.5 * sum_f xdiff[b,q,k,f]*x[b,q,h,f]
// Block = (b, 64 q, 64 k); loops all 8 heads so the xdiff tile is
// read from HBM exactly once. 8 warps = 4 q-groups x 2 k-groups;
// each warp computes a 16q x 32k piece (2 frags) + private epilogue.
// smem floats: Qt[64][68] Kt[64][68] Ls[64][68] xw[64][32] xd f4[64][65]
// =================================================================
#define LOG_SMEM_FLOATS (3 * 64 * 68 + 64 * 32 + 64 * 65 * 4)

__global__ __launch_bounds__(256) void logits_wmma(
    const float* __restrict__ qp, const float* __restrict__ kp,
    const float* __restrict__ xs, const float* __restrict__ xdiff,
    float* __restrict__ attn)
{
    extern __shared__ float sm[];
    float*  Qt = sm;                         // 4352
    float*  Kt = sm + 4352;                  // 4352
    float*  Ls = sm + 8704;                  // 4352
    float*  xw = sm + 13056;                 // 2048
    float4* xd = (float4*)(sm + 15104);      // [64][65] float4

    const int tid  = threadIdx.x;
    const int w    = tid >> 5;
    const int lane = tid & 31;
    const int wq   = w & 3;        // q-group: rows wq*16..wq*16+15
    const int wk   = w >> 2;       // k-group: cols wk*32..wk*32+31
    const int b  = blockIdx.z;
    const int q0 = blockIdx.y * 64;
    const int k0 = blockIdx.x * 64;

    // xdiff tile [64q][64k] float4 (F=4 contiguous) — once per block
    {
        const float4* xdg = (const float4*)xdiff;
#pragma unroll
        for (int r = 0; r < 16; r++) {
            int l  = tid + 256 * r;
            int qi = l >> 6, kj = l & 63;
            xd[qi * 65 + kj] = xdg[((size_t)(b * S_ + q0 + qi)) * S_ + k0 + kj];
        }
    }
    // x tile [64q][32]
#pragma unroll
    for (int r = 0; r < 2; r++) {
        int l = tid + 256 * r;
        int qi = l >> 3, c4 = (l & 7) * 4;
        *(float4*)&xw[qi * 32 + c4] =
            *(const float4*)&xs[(size_t)(b * S_ + q0 + qi) * 32 + c4];
    }
    __syncthreads();

    for (int h = 0; h < H_; h++) {
        // load Q/K tiles for this head: [64][64] each, 4 float4/thread
#pragma unroll
        for (int r = 0; r < 4; r++) {
            int l = tid + 256 * r;
            int qi = l >> 4, d4 = (l & 15) * 4;
            *(float4*)&Qt[qi * 68 + d4] =
                *(const float4*)&qp[(size_t)(b * S_ + q0 + qi) * DA_ + h * DEP_ + d4];
            *(float4*)&Kt[qi * 68 + d4] =
                *(const float4*)&kp[(size_t)(b * S_ + k0 + qi) * DA_ + h * DEP_ + d4];
        }
        __syncthreads();

        FragC acc[2];
#pragma unroll
        for (int j = 0; j < 2; j++) wmma::fill_fragment(acc[j], 0.0f);

#pragma unroll
        for (int ds = 0; ds < 8; ds++) {
            FragA a;
            wmma::load_matrix_sync(a, &Qt[(wq * 16) * 68 + ds * 8], 68);
            cvt_tf32(a);
#pragma unroll
            for (int j = 0; j < 2; j++) {
                FragBc bf;   // K col-major: elem(d, kc) at Kt[kc*68 + d]
                wmma::load_matrix_sync(bf, &Kt[(wk * 32 + j * 16) * 68 + ds * 8], 68);
                cvt_tf32(bf);
                wmma::mma_sync(acc[j], a, bf, acc[j]);
            }
        }

        // warp-private epilogue on its own 16q x 32k region of Ls
#pragma unroll
        for (int j = 0; j < 2; j++)
            wmma::store_matrix_sync(&Ls[(wq * 16) * 68 + wk * 32 + j * 16],
                                    acc[j], 68, wmma::mem_row_major);
        __syncwarp();

#pragma unroll
        for (int r = 0; r < 4; r++) {
            int idx  = lane + 32 * r;            // 0..127 = 16 rows x 8 f4
            int qi   = idx >> 3;                 // 0..15
            int kj4  = wk * 32 + (idx & 7) * 4;  // this warp's k columns
            int qrow = wq * 16 + qi;
            float4 lv = *(float4*)&Ls[qrow * 68 + kj4];
            float4 xh = *(float4*)&xw[qrow * 32 + h * 4];
            float o[4];
            float* lp = &lv.x;
#pragma unroll
            for (int t = 0; t < 4; t++) {
                float4 xv = xd[qrow * 65 + kj4 + t];
                float bias = xv.x * xh.x + xv.y * xh.y + xv.z * xh.z + xv.w * xh.w;
                o[t] = lp[t] * 0.125f + bias * 0.5f;
            }
            *(float4*)&attn[((size_t)((b * H_ + h) * S_ + q0 + qrow)) * S_ +
                            k0 + kj4] = make_float4(o[0], o[1], o[2], o[3]);
        }
        __syncthreads();   // before next head overwrites Qt/Kt/Ls
    }
}

// =================================================================
// PV: ctx[b,q,h*64+d] = sum_k attn[b,h,q,k] * vp[b,k,h*64+d]
// Block = (128 q, bh). Warp w: q rows w*16, all 64 d. BK=32.
// =================================================================
__global__ __launch_bounds__(256) void pv_wmma(
    const float* __restrict__ attn, const float* __restrict__ vp,
    float* __restrict__ ctx)
{
    extern __shared__ float sm[];
    float* At = sm;             // [128][36]
    float* Vt = sm + 128 * 36;  // [32][68]

    const int tid = threadIdx.x;
    const int w   = tid >> 5;
    const int bh  = blockIdx.y;
    const int b   = bh >> 3, h = bh & 7;
    const int q0  = blockIdx.x * 128;

    FragC acc[4];
#pragma unroll
    for (int j = 0; j < 4; j++) wmma::fill_fragment(acc[j], 0.0f);

    for (int c = 0; c < S_ / 32; c++) {
        // attn tile 128 x 32: 4 float4/thread
#pragma unroll
        for (int r = 0; r < 4; r++) {
            int idx = tid + 256 * r;
            int qi = idx >> 3, k4 = (idx & 7) * 4;
            *(float4*)&At[qi * 36 + k4] =
                *(const float4*)&attn[((size_t)bh * S_ + q0 + qi) * S_ + c * 32 + k4];
        }
        // V tile 32 x 64: 2 float4/thread
#pragma unroll
        for (int r = 0; r < 2; r++) {
            int idx = tid + 256 * r;
            int kk = idx >> 4, d4 = (idx & 15) * 4;
            *(float4*)&Vt[kk * 68 + d4] =
                *(const float4*)&vp[(size_t)(b * S_ + c * 32 + kk) * DA_ + h * DEP_ + d4];
        }
        __syncthreads();

#pragma unroll
        for (int ds = 0; ds < 4; ds++) {
            FragA a;
            wmma::load_matrix_sync(a, &At[(w * 16) * 36 + ds * 8], 36);
            cvt_tf32(a);
#pragma unroll
            for (int j = 0; j < 4; j++) {
                FragB bf;
                wmma::load_matrix_sync(bf, &Vt[ds * 8 * 68 + j * 16], 68);
                cvt_tf32(bf);
                wmma::mma_sync(acc[j], a, bf, acc[j]);
            }
        }
        __syncthreads();
    }

    // store straight to global (row-major, ld = DA_)
#pragma unroll
    for (int j = 0; j < 4; j++)
        wmma::store_matrix_sync(
            &ctx[(size_t)(b * S_ + q0 + w * 16) * DA_ + h * DEP_ + j * 16],
            acc[j], DA_, wmma::mem_row_major);
}

// =================================================================
// Softmax over last dim (2048) — one block per row, all in registers
// =================================================================
__global__ __launch_bounds__(256) void softmax_kernel(float* __restrict__ attn)
{
    __shared__ float red[8];
    const size_t row = blockIdx.x;
    float4* p = (float4*)(attn + row * (size_t)S_);
    const int tid = threadIdx.x;

    float4 v0 = p[tid];
    float4 v1 = p[tid + 256];

    float m = fmaxf(fmaxf(fmaxf(v0.x, v0.y), fmaxf(v0.z, v0.w)),
                    fmaxf(fmaxf(v1.x, v1.y), fmaxf(v1.z, v1.w)));
#pragma unroll
    for (int o = 16; o > 0; o >>= 1) m = fmaxf(m, __shfl_xor_sync(0xffffffffu, m, o));
    if ((tid & 31) == 0) red[tid >> 5] = m;
    __syncthreads();
    m = red[0];
#pragma unroll
    for (int i = 1; i < 8; i++) m = fmaxf(m, red[i]);
    __syncthreads();

    v0.x = __expf(v0.x - m); v0.y = __expf(v0.y - m);
    v0.z = __expf(v0.z - m); v0.w = __expf(v0.w - m);
    v1.x = __expf(v1.x - m); v1.y = __expf(v1.y - m);
    v1.z = __expf(v1.z - m); v1.w = __expf(v1.w - m);

    float s = (v0.x + v0.y + v0.z + v0.w) + (v1.x + v1.y + v1.z + v1.w);
#pragma unroll
    for (int o = 16; o > 0; o >>= 1) s += __shfl_xor_sync(0xffffffffu, s, o);
    if ((tid & 31) == 0) red[tid >> 5] = s;
    __syncthreads();
    s = red[0];
#pragma unroll
    for (int i = 1; i < 8; i++) s += red[i];

    float inv = 1.0f / s;
    v0.x *= inv; v0.y *= inv; v0.z *= inv; v0.w *= inv;
    v1.x *= inv; v1.y *= inv; v1.z *= inv; v1.w *= inv;
    p[tid] = v0;
    p[tid + 256] = v1;
}

// =================================================================
extern "C" void kernel_launch(void* const* d_in, const int* in_sizes, int n_in,
                              void* d_out, int out_size)
{
    const float* q     = (const float*)d_in[0];
    const float* k     = (const float*)d_in[1];
    const float* v     = (const float*)d_in[2];
    const float* xdiff = (const float*)d_in[3];
    const float* wq    = (const float*)d_in[4];
    const float* bq    = (const float*)d_in[5];
    const float* wk    = (const float*)d_in[6];
    const float* bk    = (const float*)d_in[7];
    const float* wv    = (const float*)d_in[8];
    const float* bv    = (const float*)d_in[9];
    const float* wx    = (const float*)d_in[10];
    const float* bx    = (const float*)d_in[11];
    const float* wo    = (const float*)d_in[12];
    const float* bo    = (const float*)d_in[13];

    float* out  = (float*)d_out;                        // [B,S,DM]
    float* attn = out + (size_t)BS_ * DM_;              // [B,H,S,S]

    float *qp, *kp, *vp, *xs, *ctx;
    cudaGetSymbolAddress((void**)&qp,  g_qp);
    cudaGetSymbolAddress((void**)&kp,  g_kp);
    cudaGetSymbolAddress((void**)&vp,  g_vp);
    cudaGetSymbolAddress((void**)&xs,  g_xs);
    cudaGetSymbolAddress((void**)&ctx, g_ctx);

    const int SM_G128 = 128 * 132 * 4;                        // 67584
    const int SM_G32  = (128 * 36 + 32 * 36) * 4;             // 23040
    const int SM_LOG  = LOG_SMEM_FLOATS * 4;                  // 126976
    const int SM_PV   = (128 * 36 + 32 * 68) * 4;             // 27136

    cudaFuncSetAttribute((const void*)gemm_wmma<128, 2, 4>,
                         cudaFuncAttributeMaxDynamicSharedMemorySize, SM_G128);
    cudaFuncSetAttribute((const void*)gemm_wmma<32, 8, 1>,
                         cudaFuncAttributeMaxDynamicSharedMemorySize, SM_G32);
    cudaFuncSetAttribute((const void*)logits_wmma,
                         cudaFuncAttributeMaxDynamicSharedMemorySize, SM_LOG);
    cudaFuncSetAttribute((const void*)pv_wmma,
                         cudaFuncAttributeMaxDynamicSharedMemorySize, SM_PV);

    dim3 gProj(DA_ / 128, BS_ / 128);   // (4, 64)

    // projections (tf32 WMMA)
    gemm_wmma<128, 2, 4><<<gProj, 256, SM_G128>>>(q, wq, bq, qp, BS_, DA_, DM_);
    gemm_wmma<128, 2, 4><<<gProj, 256, SM_G128>>>(k, wk, bk, kp, BS_, DA_, DM_);
    gemm_wmma<128, 2, 4><<<gProj, 256, SM_G128>>>(v, wv, bv, vp, BS_, DA_, DM_);

    // x = qp @ wx + bx   (N = 32)
    gemm_wmma<32, 8, 1><<<dim3(1, BS_ / 128), 256, SM_G32>>>(qp, wx, bx, xs,
                                                             BS_, H_ * F_, DA_);

    // logits (+ xdiff bias) -> attn
    logits_wmma<<<dim3(S_ / 64, S_ / 64, B_), 256, SM_LOG>>>(qp, kp, xs, xdiff, attn);

    // softmax in place
    softmax_kernel<<<B_ * H_ * S_, 256>>>(attn);

    // attn @ V -> ctx
    pv_wmma<<<dim3(S_ / 128, B_ * H_), 256, SM_PV>>>(attn, vp, ctx);

    // out = ctx @ wo + bo
    gemm_wmma<128, 2, 4><<<gProj, 256, SM_G128>>>(ctx, wo, bo, out, BS_, DM_, DA_);
}

// round 8
// speedup vs baseline: 1.2076x; 1.1585x over previous
#include <cuda_runtime.h>
#include <mma.h>
#include <cstdint>
#include <cstddef>

using namespace nvcuda;

// Problem dims
#define B_ 4
#define S_ 2048
#define DM_ 512
#define DA_ 512
#define H_ 8
#define F_ 4
#define DEP_ 64
#define BS_ (B_ * S_)       // 8192
#define ROWS_ (B_ * H_ * S_)  // 65536

// ---------------- scratch (no allocations allowed) ----------------
__device__ float g_qp[(size_t)BS_ * DA_];
__device__ float g_kp[(size_t)BS_ * DA_];
__device__ float g_vp[(size_t)BS_ * DA_];
__device__ float g_xs[(size_t)BS_ * (H_ * F_)];
__device__ float g_ctx[(size_t)BS_ * DA_];
__device__ float g_psum[(size_t)ROWS_ * 64];   // per-(row, k-block-half) partial sums
__device__ float g_rinv[(size_t)ROWS_];        // 1 / rowsum

typedef wmma::fragment<wmma::matrix_a, 16, 16, 8, wmma::precision::tf32, wmma::row_major> FragA;
typedef wmma::fragment<wmma::matrix_b, 16, 16, 8, wmma::precision::tf32, wmma::row_major> FragB;
typedef wmma::fragment<wmma::matrix_b, 16, 16, 8, wmma::precision::tf32, wmma::col_major> FragBc;
typedef wmma::fragment<wmma::accumulator, 16, 16, 8, float> FragC;

template <typename F>
__device__ __forceinline__ void cvt_tf32(F& f) {
#pragma unroll
    for (int i = 0; i < f.num_elements; i++)
        f.x[i] = wmma::__float_to_tf32(f.x[i]);
}

// =================================================================
// WMMA tf32 GEMM: C[M,N] = A[M,K] @ W[K,N] + bias[N]
// Block tile 128 x BN, BK=32, 256 threads (8 warps).
// =================================================================
template <int BN, int WR, int WC>
__global__ __launch_bounds__(256) void gemm_wmma(
    const float* __restrict__ A, const float* __restrict__ W,
    const float* __restrict__ bias, float* __restrict__ C,
    int M, int N, int K)
{
    constexpr int LDA = 36;
    constexpr int LDB = BN + 4;
    constexpr int MI = 128 / (WR * 16);
    constexpr int NI = BN / (WC * 16);

    extern __shared__ float sm[];
    float* As = sm;                  // [128][36]
    float* Ws = sm + 128 * LDA;      // [32][BN+4]
    float* Cs = sm;                  // epilogue reuse

    const int tid = threadIdx.x;
    const int wid = tid >> 5;
    const int warp_m = wid % WR;
    const int warp_n = wid / WR;
    const int m0 = blockIdx.y * 128;
    const int n0 = blockIdx.x * BN;

    FragC acc[MI][NI];
#pragma unroll
    for (int i = 0; i < MI; i++)
#pragma unroll
        for (int j = 0; j < NI; j++) wmma::fill_fragment(acc[i][j], 0.0f);

    for (int k0 = 0; k0 < K; k0 += 32) {
#pragma unroll
        for (int r = 0; r < 4; r++) {
            int idx = tid + 256 * r;
            int m = idx >> 3, k4 = (idx & 7) * 4;
            *(float4*)&As[m * LDA + k4] =
                *(const float4*)&A[(size_t)(m0 + m) * K + k0 + k4];
        }
#pragma unroll
        for (int r = 0; r < BN / 32; r++) {
            int idx = tid + 256 * r;
            int kk = idx / (BN / 4), n4 = (idx % (BN / 4)) * 4;
            *(float4*)&Ws[kk * LDB + n4] =
                *(const float4*)&W[(size_t)(k0 + kk) * N + n0 + n4];
        }
        __syncthreads();

#pragma unroll
        for (int ds = 0; ds < 4; ds++) {
            FragA af[MI];
#pragma unroll
            for (int i = 0; i < MI; i++) {
                wmma::load_matrix_sync(af[i],
                    &As[(warp_m * (128 / WR) + i * 16) * LDA + ds * 8], LDA);
                cvt_tf32(af[i]);
            }
            FragB bf;
#pragma unroll
            for (int j = 0; j < NI; j++) {
                wmma::load_matrix_sync(bf,
                    &Ws[ds * 8 * LDB + warp_n * (BN / WC) + j * 16], LDB);
                cvt_tf32(bf);
#pragma unroll
                for (int i = 0; i < MI; i++)
                    wmma::mma_sync(acc[i][j], af[i], bf, acc[i][j]);
            }
        }
        __syncthreads();
    }

#pragma unroll
    for (int i = 0; i < MI; i++)
#pragma unroll
        for (int j = 0; j < NI; j++)
            wmma::store_matrix_sync(
                &Cs[(warp_m * (128 / WR) + i * 16) * LDB +
                    warp_n * (BN / WC) + j * 16],
                acc[i][j], LDB, wmma::mem_row_major);
    __syncthreads();

#pragma unroll
    for (int r = 0; r < BN / 8; r++) {
        int idx = tid + 256 * r;
        int m = idx / (BN / 4), n4 = (idx % (BN / 4)) * 4;
        float4 v = *(float4*)&Cs[m * LDB + n4];
        float4 bz = *(const float4*)&bias[n0 + n4];
        v.x += bz.x; v.y += bz.y; v.z += bz.z; v.w += bz.w;
        *(float4*)&C[(size_t)(m0 + m) * N + n0 + n4] = v;
    }
}

// =================================================================
// Logits+exp: e[b,h,q,k] = exp((qh.kh)/8 + 0.5*sum_f xdiff*x), written
// unnormalized to attn; per-(row, k-half-block) partial sums -> g_psum.
// Block = (b, 64q, 64k), loops 8 heads; xdiff tile read from HBM once.
// smem: Qt[64][68] (aliased by Ls), Kt[64][68], xw[64][32], xd f4[64][65]
// = 107 KB -> 2 blocks/SM.
// =================================================================
#define LOG_SMEM_BYTES ((2 * 64 * 68 + 64 * 32) * 4 + 64 * 65 * 16)

__global__ __launch_bounds__(256) void logits_exp_wmma(
    const float* __restrict__ qp, const float* __restrict__ kp,
    const float* __restrict__ xs, const float* __restrict__ xdiff,
    float* __restrict__ attn, float* __restrict__ psum)
{
    extern __shared__ float sm[];
    float*  Qt = sm;                       // 4352 floats (also Ls)
    float*  Ls = sm;                       // alias of Qt
    float*  Kt = sm + 4352;                // 4352
    float*  xw = sm + 8704;                // 2048
    float4* xd = (float4*)(sm + 10752);    // [64][65] float4

    const int tid  = threadIdx.x;
    const int w    = tid >> 5;
    const int lane = tid & 31;
    const int wq   = w & 3;        // q-group: rows wq*16..+15
    const int wk   = w >> 2;       // k-group: cols wk*32..+31
    const int b  = blockIdx.z;
    const int q0 = blockIdx.y * 64;
    const int k0 = blockIdx.x * 64;

    // xdiff tile [64q][64k] float4 — once per block
    {
        const float4* xdg = (const float4*)xdiff;
#pragma unroll
        for (int r = 0; r < 16; r++) {
            int l  = tid + 256 * r;
            int qi = l >> 6, kj = l & 63;
            xd[qi * 65 + kj] = xdg[((size_t)(b * S_ + q0 + qi)) * S_ + k0 + kj];
        }
    }
#pragma unroll
    for (int r = 0; r < 2; r++) {
        int l = tid + 256 * r;
        int qi = l >> 3, c4 = (l & 7) * 4;
        *(float4*)&xw[qi * 32 + c4] =
            *(const float4*)&xs[(size_t)(b * S_ + q0 + qi) * 32 + c4];
    }
    __syncthreads();

    for (int h = 0; h < H_; h++) {
#pragma unroll
        for (int r = 0; r < 4; r++) {
            int l = tid + 256 * r;
            int qi = l >> 4, d4 = (l & 15) * 4;
            *(float4*)&Qt[qi * 68 + d4] =
                *(const float4*)&qp[(size_t)(b * S_ + q0 + qi) * DA_ + h * DEP_ + d4];
            *(float4*)&Kt[qi * 68 + d4] =
                *(const float4*)&kp[(size_t)(b * S_ + k0 + qi) * DA_ + h * DEP_ + d4];
        }
        __syncthreads();

        FragC acc[2];
#pragma unroll
        for (int j = 0; j < 2; j++) wmma::fill_fragment(acc[j], 0.0f);

#pragma unroll
        for (int ds = 0; ds < 8; ds++) {
            FragA a;
            wmma::load_matrix_sync(a, &Qt[(wq * 16) * 68 + ds * 8], 68);
            cvt_tf32(a);
#pragma unroll
            for (int j = 0; j < 2; j++) {
                FragBc bf;
                wmma::load_matrix_sync(bf, &Kt[(wk * 32 + j * 16) * 68 + ds * 8], 68);
                cvt_tf32(bf);
                wmma::mma_sync(acc[j], a, bf, acc[j]);
            }
        }
        __syncthreads();   // all warps done reading Qt before Ls(=Qt) stores

#pragma unroll
        for (int j = 0; j < 2; j++)
            wmma::store_matrix_sync(&Ls[(wq * 16) * 68 + wk * 32 + j * 16],
                                    acc[j], 68, wmma::mem_row_major);
        __syncwarp();

#pragma unroll
        for (int r = 0; r < 4; r++) {
            int idx  = lane + 32 * r;            // 16 rows x 8 f4 per warp
            int qi   = (idx >> 3);               // (lane>>3) + 4r
            int kj4  = wk * 32 + (idx & 7) * 4;
            int qrow = wq * 16 + qi;
            float4 lv = *(float4*)&Ls[qrow * 68 + kj4];
            float4 xh = *(float4*)&xw[qrow * 32 + h * 4];
            float e[4];
            float* lp = &lv.x;
            float tsum = 0.0f;
#pragma unroll
            for (int t = 0; t < 4; t++) {
                float4 xv = xd[qrow * 65 + kj4 + t];
                float bias = xv.x * xh.x + xv.y * xh.y + xv.z * xh.z + xv.w * xh.w;
                e[t] = __expf(lp[t] * 0.125f + bias * 0.5f);
                tsum += e[t];
            }
            size_t row_g = (size_t)(b * H_ + h) * S_ + q0 + qrow;
            *(float4*)&attn[row_g * S_ + k0 + kj4] =
                make_float4(e[0], e[1], e[2], e[3]);
            // reduce tsum across the 8 lanes sharing this row
            tsum += __shfl_down_sync(0xffffffffu, tsum, 4, 8);
            tsum += __shfl_down_sync(0xffffffffu, tsum, 2, 8);
            tsum += __shfl_down_sync(0xffffffffu, tsum, 1, 8);
            if ((lane & 7) == 0)
                psum[row_g * 64 + blockIdx.x * 2 + wk] = tsum;
        }
        __syncthreads();   // before next head overwrites Qt/Kt/Ls
    }
}

// =================================================================
// Row-sum reduce: g_rinv[row] = 1 / sum(g_psum[row][0..63])
// One warp per row.
// =================================================================
__global__ __launch_bounds__(256) void rowsum_kernel(
    const float* __restrict__ psum, float* __restrict__ rinv)
{
    const int wir  = threadIdx.x >> 5;            // warp in block
    const int lane = threadIdx.x & 31;
    const size_t row = (size_t)blockIdx.x * 8 + wir;
    const float* p = psum + row * 64;
    float s = p[lane] + p[lane + 32];
#pragma unroll
    for (int o = 16; o > 0; o >>= 1) s += __shfl_xor_sync(0xffffffffu, s, o);
    if (lane == 0) rinv[row] = 1.0f / s;
}

// =================================================================
// PV fused with normalization: reads unnormalized e from attn, writes
// p = e * rinv back in place, accumulates ctx = p @ V via wmma.
// Block = (128 q, bh). BK = 64.
// =================================================================
__global__ __launch_bounds__(256) void pv_wmma(
    float* __restrict__ attn, const float* __restrict__ vp,
    const float* __restrict__ rinv, float* __restrict__ ctx)
{
    extern __shared__ float sm[];
    float* At = sm;                  // [128][68]
    float* Vt = sm + 128 * 68;       // [64][68]
    float* rs = sm + 128 * 68 + 64 * 68;  // [128]

    const int tid = threadIdx.x;
    const int w   = tid >> 5;
    const int bh  = blockIdx.y;
    const int b   = bh >> 3, h = bh & 7;
    const int q0  = blockIdx.x * 128;

    if (tid < 128) rs[tid] = rinv[(size_t)bh * S_ + q0 + tid];
    __syncthreads();

    FragC acc[4];
#pragma unroll
    for (int j = 0; j < 4; j++) wmma::fill_fragment(acc[j], 0.0f);

    for (int c = 0; c < S_ / 64; c++) {
        // attn tile 128 x 64: normalize during load, write p back in place
#pragma unroll
        for (int r = 0; r < 8; r++) {
            int idx = tid + 256 * r;
            int qi = idx >> 4, k4 = (idx & 15) * 4;
            float* gp = &attn[((size_t)bh * S_ + q0 + qi) * S_ + c * 64 + k4];
            float4 v = *(float4*)gp;
            float riv = rs[qi];
            v.x *= riv; v.y *= riv; v.z *= riv; v.w *= riv;
            *(float4*)&At[qi * 68 + k4] = v;
            *(float4*)gp = v;
        }
        // V tile 64 x 64
#pragma unroll
        for (int r = 0; r < 4; r++) {
            int idx = tid + 256 * r;
            int kk = idx >> 4, d4 = (idx & 15) * 4;
            *(float4*)&Vt[kk * 68 + d4] =
                *(const float4*)&vp[(size_t)(b * S_ + c * 64 + kk) * DA_ + h * DEP_ + d4];
        }
        __syncthreads();

#pragma unroll
        for (int ds = 0; ds < 8; ds++) {
            FragA a;
            wmma::load_matrix_sync(a, &At[(w * 16) * 68 + ds * 8], 68);
            cvt_tf32(a);
#pragma unroll
            for (int j = 0; j < 4; j++) {
                FragB bf;
                wmma::load_matrix_sync(bf, &Vt[ds * 8 * 68 + j * 16], 68);
                cvt_tf32(bf);
                wmma::mma_sync(acc[j], a, bf, acc[j]);
            }
        }
        __syncthreads();
    }

#pragma unroll
    for (int j = 0; j < 4; j++)
        wmma::store_matrix_sync(
            &ctx[(size_t)(b * S_ + q0 + w * 16) * DA_ + h * DEP_ + j * 16],
            acc[j], DA_, wmma::mem_row_major);
}

// =================================================================
extern "C" void kernel_launch(void* const* d_in, const int* in_sizes, int n_in,
                              void* d_out, int out_size)
{
    const float* q     = (const float*)d_in[0];
    const float* k     = (const float*)d_in[1];
    const float* v     = (const float*)d_in[2];
    const float* xdiff = (const float*)d_in[3];
    const float* wq    = (const float*)d_in[4];
    const float* bq    = (const float*)d_in[5];
    const float* wk    = (const float*)d_in[6];
    const float* bk    = (const float*)d_in[7];
    const float* wv    = (const float*)d_in[8];
    const float* bv    = (const float*)d_in[9];
    const float* wx    = (const float*)d_in[10];
    const float* bx    = (const float*)d_in[11];
    const float* wo    = (const float*)d_in[12];
    const float* bo    = (const float*)d_in[13];

    float* out  = (float*)d_out;                        // [B,S,DM]
    float* attn = out + (size_t)BS_ * DM_;              // [B,H,S,S]

    float *qp, *kp, *vp, *xs, *ctx, *psum, *rinv;
    cudaGetSymbolAddress((void**)&qp,   g_qp);
    cudaGetSymbolAddress((void**)&kp,   g_kp);
    cudaGetSymbolAddress((void**)&vp,   g_vp);
    cudaGetSymbolAddress((void**)&xs,   g_xs);
    cudaGetSymbolAddress((void**)&ctx,  g_ctx);
    cudaGetSymbolAddress((void**)&psum, g_psum);
    cudaGetSymbolAddress((void**)&rinv, g_rinv);

    const int SM_G128 = 128 * 132 * 4;                        // 67584
    const int SM_G32  = (128 * 36 + 32 * 36) * 4;             // 23040
    const int SM_LOG  = LOG_SMEM_BYTES;                       // 109568
    const int SM_PV   = (128 * 68 + 64 * 68 + 128) * 4;       // 52736

    cudaFuncSetAttribute((const void*)gemm_wmma<128, 2, 4>,
                         cudaFuncAttributeMaxDynamicSharedMemorySize, SM_G128);
    cudaFuncSetAttribute((const void*)gemm_wmma<32, 8, 1>,
                         cudaFuncAttributeMaxDynamicSharedMemorySize, SM_G32);
    cudaFuncSetAttribute((const void*)logits_exp_wmma,
                         cudaFuncAttributeMaxDynamicSharedMemorySize, SM_LOG);
    cudaFuncSetAttribute((const void*)pv_wmma,
                         cudaFuncAttributeMaxDynamicSharedMemorySize, SM_PV);

    dim3 gProj(DA_ / 128, BS_ / 128);   // (4, 64)

    // projections (tf32 WMMA)
    gemm_wmma<128, 2, 4><<<gProj, 256, SM_G128>>>(q, wq, bq, qp, BS_, DA_, DM_);
    gemm_wmma<128, 2, 4><<<gProj, 256, SM_G128>>>(k, wk, bk, kp, BS_, DA_, DM_);
    gemm_wmma<128, 2, 4><<<gProj, 256, SM_G128>>>(v, wv, bv, vp, BS_, DA_, DM_);

    // x = qp @ wx + bx
    gemm_wmma<32, 8, 1><<<dim3(1, BS_ / 128), 256, SM_G32>>>(qp, wx, bx, xs,
                                                             BS_, H_ * F_, DA_);

    // logits + bias + exp -> attn (unnormalized) + partial sums
    logits_exp_wmma<<<dim3(S_ / 64, S_ / 64, B_), 256, SM_LOG>>>(
        qp, kp, xs, xdiff, attn, psum);

    // rowsum -> 1/s
    rowsum_kernel<<<ROWS_ / 8, 256>>>(psum, rinv);

    // PV + in-place normalization of attn
    pv_wmma<<<dim3(S_ / 128, B_ * H_), 256, SM_PV>>>(attn, vp, rinv, ctx);

    // out = ctx @ wo + bo
    gemm_wmma<128, 2, 4><<<gProj, 256, SM_G128>>>(ctx, wo, bo, out, BS_, DM_, DA_);
}

// round 9
// speedup vs baseline: 1.4714x; 1.2184x over previous
#include <cuda_runtime.h>
#include <mma.h>
#include <cstdint>
#include <cstddef>

using namespace nvcuda;

// Problem dims
#define B_ 4
#define S_ 2048
#define DM_ 512
#define DA_ 512
#define H_ 8
#define F_ 4
#define DEP_ 64
#define BS_ (B_ * S_)         // 8192
#define ROWS_ (B_ * H_ * S_)  // 65536

// ---------------- scratch (no allocations allowed) ----------------
__device__ float g_qp[(size_t)BS_ * DA_];
__device__ float g_kp[(size_t)BS_ * DA_];
__device__ float g_vp[(size_t)BS_ * DA_];
__device__ float g_xs[(size_t)BS_ * (H_ * F_)];
__device__ float g_ctx[(size_t)BS_ * DA_];
__device__ float g_psum[(size_t)ROWS_ * 128];  // per-(row, 16k-slot) partials
__device__ float g_rinv[(size_t)ROWS_];        // 1 / rowsum

typedef wmma::fragment<wmma::matrix_a, 16, 16, 8, wmma::precision::tf32, wmma::row_major> FragA;
typedef wmma::fragment<wmma::matrix_b, 16, 16, 8, wmma::precision::tf32, wmma::row_major> FragB;
typedef wmma::fragment<wmma::matrix_b, 16, 16, 8, wmma::precision::tf32, wmma::col_major> FragBc;
typedef wmma::fragment<wmma::accumulator, 16, 16, 8, float> FragC;

template <typename F>
__device__ __forceinline__ void cvt_tf32(F& f) {
#pragma unroll
    for (int i = 0; i < f.num_elements; i++)
        f.x[i] = wmma::__float_to_tf32(f.x[i]);
}

// ---------------- cp.async helpers ----------------
__device__ __forceinline__ void cp16(float* dst_smem, const float* src_g) {
    uint32_t d = (uint32_t)__cvta_generic_to_shared(dst_smem);
    asm volatile("cp.async.cg.shared.global [%0], [%1], 16;"
                 :: "r"(d), "l"(src_g) : "memory");
}
__device__ __forceinline__ void cp_commit() {
    asm volatile("cp.async.commit_group;" ::: "memory");
}
template <int N>
__device__ __forceinline__ void cp_wait() {
    asm volatile("cp.async.wait_group %0;" :: "n"(N) : "memory");
}

// =================================================================
// WMMA tf32 GEMM, 2-stage cp.async pipeline.
// C[M,N] = A[M,K] @ W[K,N] + bias[N]; block tile 128 x BN, BK=32.
// =================================================================
template <int BN, int WR, int WC>
__global__ __launch_bounds__(256) void gemm_wmma(
    const float* __restrict__ A, const float* __restrict__ W,
    const float* __restrict__ bias, float* __restrict__ C,
    int M, int N, int K)
{
    constexpr int LDA = 36;
    constexpr int LDB = BN + 4;
    constexpr int SA  = 128 * LDA;   // floats per A stage
    constexpr int SW  = 32 * LDB;    // floats per W stage
    constexpr int MI = 128 / (WR * 16);
    constexpr int NI = BN / (WC * 16);

    extern __shared__ float sm[];
    float* Cs = sm;   // epilogue reuse of stage region

    const int tid = threadIdx.x;
    const int wid = tid >> 5;
    const int warp_m = wid % WR;
    const int warp_n = wid / WR;
    const int m0 = blockIdx.y * 128;
    const int n0 = blockIdx.x * BN;
    const int nc = K / 32;

    auto loadStage = [&](int st, int c) {
        float* As = sm + st * SA;
        float* Ws = sm + 2 * SA + st * SW;
#pragma unroll
        for (int r = 0; r < 4; r++) {
            int idx = tid + 256 * r;
            int m = idx >> 3, k4 = (idx & 7) * 4;
            cp16(&As[m * LDA + k4], &A[(size_t)(m0 + m) * K + c * 32 + k4]);
        }
#pragma unroll
        for (int r = 0; r < BN / 32; r++) {
            int idx = tid + 256 * r;
            int kk = idx / (BN / 4), n4 = (idx % (BN / 4)) * 4;
            cp16(&Ws[kk * LDB + n4], &W[(size_t)(c * 32 + kk) * N + n0 + n4]);
        }
    };

    FragC acc[MI][NI];
#pragma unroll
    for (int i = 0; i < MI; i++)
#pragma unroll
        for (int j = 0; j < NI; j++) wmma::fill_fragment(acc[i][j], 0.0f);

    loadStage(0, 0);
    cp_commit();

    for (int c = 0; c < nc; c++) {
        if (c + 1 < nc) {
            loadStage((c + 1) & 1, c + 1);
            cp_commit();
            cp_wait<1>();
        } else {
            cp_wait<0>();
        }
        __syncthreads();

        const float* As = sm + (c & 1) * SA;
        const float* Ws = sm + 2 * SA + (c & 1) * SW;
#pragma unroll
        for (int ds = 0; ds < 4; ds++) {
            FragA af[MI];
#pragma unroll
            for (int i = 0; i < MI; i++) {
                wmma::load_matrix_sync(af[i],
                    &As[(warp_m * (128 / WR) + i * 16) * LDA + ds * 8], LDA);
                cvt_tf32(af[i]);
            }
            FragB bf;
#pragma unroll
            for (int j = 0; j < NI; j++) {
                wmma::load_matrix_sync(bf,
                    &Ws[ds * 8 * LDB + warp_n * (BN / WC) + j * 16], LDB);
                cvt_tf32(bf);
#pragma unroll
                for (int i = 0; i < MI; i++)
                    wmma::mma_sync(acc[i][j], af[i], bf, acc[i][j]);
            }
        }
        __syncthreads();
    }

    // epilogue
#pragma unroll
    for (int i = 0; i < MI; i++)
#pragma unroll
        for (int j = 0; j < NI; j++)
            wmma::store_matrix_sync(
                &Cs[(warp_m * (128 / WR) + i * 16) * LDB +
                    warp_n * (BN / WC) + j * 16],
                acc[i][j], LDB, wmma::mem_row_major);
    __syncthreads();

#pragma unroll
    for (int r = 0; r < BN / 8; r++) {
        int idx = tid + 256 * r;
        int m = idx / (BN / 4), n4 = (idx % (BN / 4)) * 4;
        float4 v = *(float4*)&Cs[m * LDB + n4];
        float4 bz = *(const float4*)&bias[n0 + n4];
        v.x += bz.x; v.y += bz.y; v.z += bz.z; v.w += bz.w;
        *(float4*)&C[(size_t)(m0 + m) * N + n0 + n4] = v;
    }
}

// =================================================================
// Logits+exp, pipelined across heads.
// Block = (b, 64q, 32k); 8 heads accumulate while next head's Q/K
// tiles stream in via cp.async. xdiff tile read from HBM exactly once.
// Warp w: q-group w&3 (16 rows), k-half w>>2 (16 cols), 1 frag.
// smem floats: Qt[2][64*68], Kt[2][32*68], xw[64*32], xd f4[64][33]
// = 94208 B -> 2 blocks/SM.
// =================================================================
#define LOG_SMEM_BYTES 94208

__global__ __launch_bounds__(256) void logits_exp_wmma(
    const float* __restrict__ qp, const float* __restrict__ kp,
    const float* __restrict__ xs, const float* __restrict__ xdiff,
    float* __restrict__ attn, float* __restrict__ psum)
{
    constexpr int SQ = 64 * 68;   // 4352
    constexpr int SK = 32 * 68;   // 2176

    extern __shared__ float sm[];
    float*  QtB = sm;                    // 2 stages
    float*  KtB = sm + 2 * SQ;           // 2 stages
    float*  xw  = sm + 2 * SQ + 2 * SK;  // 2048
    float4* xd  = (float4*)(xw + 2048);  // [64][33] f4

    const int tid  = threadIdx.x;
    const int w    = tid >> 5;
    const int lane = tid & 31;
    const int wq   = w & 3;     // q-group
    const int wkh  = w >> 2;    // k-half (16 cols)
    const int b  = blockIdx.z;
    const int q0 = blockIdx.y * 64;
    const int k0 = blockIdx.x * 32;

    auto loadQK = [&](int st, int h) {
        float* Qt = QtB + st * SQ;
        float* Kt = KtB + st * SK;
#pragma unroll
        for (int r = 0; r < 4; r++) {
            int idx = tid + 256 * r;
            int qi = idx >> 4, d4 = (idx & 15) * 4;
            cp16(&Qt[qi * 68 + d4],
                 &qp[(size_t)(b * S_ + q0 + qi) * DA_ + h * DEP_ + d4]);
        }
#pragma unroll
        for (int r = 0; r < 2; r++) {
            int idx = tid + 256 * r;
            int kk = idx >> 4, d4 = (idx & 15) * 4;
            cp16(&Kt[kk * 68 + d4],
                 &kp[(size_t)(b * S_ + k0 + kk) * DA_ + h * DEP_ + d4]);
        }
    };

    // one-time tiles: xdiff [64q][32k] f4 + x [64q][32]
    {
        const float4* xdg = (const float4*)xdiff;
#pragma unroll
        for (int r = 0; r < 8; r++) {
            int idx = tid + 256 * r;
            int qi = idx >> 5, kj = idx & 31;
            cp16((float*)&xd[qi * 33 + kj],
                 (const float*)&xdg[((size_t)(b * S_ + q0 + qi)) * S_ + k0 + kj]);
        }
#pragma unroll
        for (int r = 0; r < 2; r++) {
            int idx = tid + 256 * r;
            int qi = idx >> 3, c4 = (idx & 7) * 4;
            cp16(&xw[qi * 32 + c4],
                 &xs[(size_t)(b * S_ + q0 + qi) * 32 + c4]);
        }
    }
    loadQK(0, 0);
    cp_commit();

    for (int h = 0; h < H_; h++) {
        if (h + 1 < H_) {
            loadQK((h + 1) & 1, h + 1);
            cp_commit();
            cp_wait<1>();
        } else {
            cp_wait<0>();
        }
        __syncthreads();

        float* Qt = QtB + (h & 1) * SQ;
        float* Kt = KtB + (h & 1) * SK;
        float* Ls = Qt;   // alias, written after MMA

        FragC acc;
        wmma::fill_fragment(acc, 0.0f);
#pragma unroll
        for (int ds = 0; ds < 8; ds++) {
            FragA a;
            wmma::load_matrix_sync(a, &Qt[(wq * 16) * 68 + ds * 8], 68);
            cvt_tf32(a);
            FragBc bf;
            wmma::load_matrix_sync(bf, &Kt[(wkh * 16) * 68 + ds * 8], 68);
            cvt_tf32(bf);
            wmma::mma_sync(acc, a, bf, acc);
        }
        __syncthreads();   // all Qt/Kt reads done before Ls overwrite

        wmma::store_matrix_sync(&Ls[(wq * 16) * 68 + wkh * 16], acc,
                                68, wmma::mem_row_major);
        __syncwarp();

        // epilogue: warp owns 16 rows x 16 cols (4 f4 groups per row)
#pragma unroll
        for (int r = 0; r < 2; r++) {
            int idx = lane + 32 * r;        // 0..63
            int qi = idx >> 2;              // 0..15
            int g  = idx & 3;               // f4 group within 16-col half
            int qrow = wq * 16 + qi;
            int fcol = (wkh * 4 + g) * 4;   // 0..28 within 32-col tile
            float4 lv = *(float4*)&Ls[qrow * 68 + fcol];
            float4 xh = *(float4*)&xw[qrow * 32 + h * 4];
            float e[4];
            float* lp = &lv.x;
            float tsum = 0.0f;
#pragma unroll
            for (int t = 0; t < 4; t++) {
                float4 xv = xd[qrow * 33 + fcol + t];
                float bias = xv.x * xh.x + xv.y * xh.y + xv.z * xh.z + xv.w * xh.w;
                e[t] = __expf(lp[t] * 0.125f + bias * 0.5f);
                tsum += e[t];
            }
            size_t row_g = (size_t)(b * H_ + h) * S_ + q0 + qrow;
            *(float4*)&attn[row_g * S_ + k0 + fcol] =
                make_float4(e[0], e[1], e[2], e[3]);
            tsum += __shfl_down_sync(0xffffffffu, tsum, 2, 4);
            tsum += __shfl_down_sync(0xffffffffu, tsum, 1, 4);
            if ((lane & 3) == 0)
                psum[row_g * 128 + blockIdx.x * 2 + wkh] = tsum;
        }
        __syncthreads();   // Ls reads done before next head's cp lands here
    }
}

// =================================================================
// Row-sum reduce: g_rinv[row] = 1 / sum(g_psum[row][0..127])
// =================================================================
__global__ __launch_bounds__(256) void rowsum_kernel(
    const float* __restrict__ psum, float* __restrict__ rinv)
{
    const int wir  = threadIdx.x >> 5;
    const int lane = threadIdx.x & 31;
    const size_t row = (size_t)blockIdx.x * 8 + wir;
    const float* p = psum + row * 128;
    float s = (p[lane] + p[lane + 32]) + (p[lane + 64] + p[lane + 96]);
#pragma unroll
    for (int o = 16; o > 0; o >>= 1) s += __shfl_xor_sync(0xffffffffu, s, o);
    if (lane == 0) rinv[row] = 1.0f / s;
}

// =================================================================
// PV, pipelined: ctx = (e @ V) * rinv ; also writes p = e*rinv back
// to attn in place. Block = (128q, bh), BK=32, 64 chunks, 2 stages.
// smem: At[2][128*36], Vt[2][32*68], rs[128] = 54784 B.
// =================================================================
#define PV_SMEM_BYTES 54784

__global__ __launch_bounds__(256) void pv_wmma(
    float* __restrict__ attn, const float* __restrict__ vp,
    const float* __restrict__ rinv, float* __restrict__ ctx)
{
    constexpr int SA = 128 * 36;   // 4608
    constexpr int SV = 32 * 68;    // 2176

    extern __shared__ float sm[];
    float* AtB = sm;
    float* VtB = sm + 2 * SA;
    float* rs  = sm + 2 * SA + 2 * SV;   // [128]
    float* Cs  = sm;                     // epilogue reuse (128*68 <= 2*SA)

    const int tid = threadIdx.x;
    const int w   = tid >> 5;
    const int bh  = blockIdx.y;
    const int b   = bh >> 3, h = bh & 7;
    const int q0  = blockIdx.x * 128;

    if (tid < 128) rs[tid] = rinv[(size_t)bh * S_ + q0 + tid];

    auto loadChunk = [&](int st, int c) {
        float* At = AtB + st * SA;
        float* Vt = VtB + st * SV;
#pragma unroll
        for (int r = 0; r < 4; r++) {
            int idx = tid + 256 * r;
            int qi = idx >> 3, k4 = (idx & 7) * 4;
            cp16(&At[qi * 36 + k4],
                 &attn[((size_t)bh * S_ + q0 + qi) * S_ + c * 32 + k4]);
        }
#pragma unroll
        for (int r = 0; r < 2; r++) {
            int idx = tid + 256 * r;
            int kk = idx >> 4, d4 = (idx & 15) * 4;
            cp16(&Vt[kk * 68 + d4],
                 &vp[(size_t)(b * S_ + c * 32 + kk) * DA_ + h * DEP_ + d4]);
        }
    };

    FragC acc[4];
#pragma unroll
    for (int j = 0; j < 4; j++) wmma::fill_fragment(acc[j], 0.0f);

    loadChunk(0, 0);
    cp_commit();

    for (int c = 0; c < S_ / 32; c++) {
        if (c + 1 < S_ / 32) {
            loadChunk((c + 1) & 1, c + 1);
            cp_commit();
            cp_wait<1>();
        } else {
            cp_wait<0>();
        }
        __syncthreads();

        const float* At = AtB + (c & 1) * SA;
        const float* Vt = VtB + (c & 1) * SV;

        // write p = e * rinv back to attn (raw e stays in smem for MMA)
#pragma unroll
        for (int r = 0; r < 4; r++) {
            int idx = tid + 256 * r;
            int qi = idx >> 3, k4 = (idx & 7) * 4;
            float4 v = *(const float4*)&At[qi * 36 + k4];
            float riv = rs[qi];
            v.x *= riv; v.y *= riv; v.z *= riv; v.w *= riv;
            *(float4*)&attn[((size_t)bh * S_ + q0 + qi) * S_ + c * 32 + k4] = v;
        }

#pragma unroll
        for (int ds = 0; ds < 4; ds++) {
            FragA a;
            wmma::load_matrix_sync(a, &At[(w * 16) * 36 + ds * 8], 36);
            cvt_tf32(a);
#pragma unroll
            for (int j = 0; j < 4; j++) {
                FragB bf;
                wmma::load_matrix_sync(bf, &Vt[ds * 8 * 68 + j * 16], 68);
                cvt_tf32(bf);
                wmma::mma_sync(acc[j], a, bf, acc[j]);
            }
        }
        __syncthreads();
    }

    // epilogue: stage ctx tile in smem, scale rows by rinv, store
#pragma unroll
    for (int j = 0; j < 4; j++)
        wmma::store_matrix_sync(&Cs[(w * 16) * 68 + j * 16], acc[j],
                                68, wmma::mem_row_major);
    __syncthreads();

#pragma unroll
    for (int r = 0; r < 8; r++) {
        int idx = tid + 256 * r;
        int qi = idx >> 4, d4 = (idx & 15) * 4;
        float4 v = *(float4*)&Cs[qi * 68 + d4];
        float riv = rs[qi];
        v.x *= riv; v.y *= riv; v.z *= riv; v.w *= riv;
        *(float4*)&ctx[(size_t)(b * S_ + q0 + qi) * DA_ + h * DEP_ + d4] = v;
    }
}

// =================================================================
extern "C" void kernel_launch(void* const* d_in, const int* in_sizes, int n_in,
                              void* d_out, int out_size)
{
    const float* q     = (const float*)d_in[0];
    const float* k     = (const float*)d_in[1];
    const float* v     = (const float*)d_in[2];
    const float* xdiff = (const float*)d_in[3];
    const float* wq    = (const float*)d_in[4];
    const float* bq    = (const float*)d_in[5];
    const float* wk    = (const float*)d_in[6];
    const float* bk    = (const float*)d_in[7];
    const float* wv    = (const float*)d_in[8];
    const float* bv    = (const float*)d_in[9];
    const float* wx    = (const float*)d_in[10];
    const float* bx    = (const float*)d_in[11];
    const float* wo    = (const float*)d_in[12];
    const float* bo    = (const float*)d_in[13];

    float* out  = (float*)d_out;                        // [B,S,DM]
    float* attn = out + (size_t)BS_ * DM_;              // [B,H,S,S]

    float *qp, *kp, *vp, *xs, *ctx, *psum, *rinv;
    cudaGetSymbolAddress((void**)&qp,   g_qp);
    cudaGetSymbolAddress((void**)&kp,   g_kp);
    cudaGetSymbolAddress((void**)&vp,   g_vp);
    cudaGetSymbolAddress((void**)&xs,   g_xs);
    cudaGetSymbolAddress((void**)&ctx,  g_ctx);
    cudaGetSymbolAddress((void**)&psum, g_psum);
    cudaGetSymbolAddress((void**)&rinv, g_rinv);

    const int SM_G128 = (2 * 128 * 36 + 2 * 32 * 132) * 4;   // 70656
    const int SM_G32  = (2 * 128 * 36 + 2 * 32 * 36) * 4;    // 46080
    const int SM_LOG  = LOG_SMEM_BYTES;                      // 94208
    const int SM_PV   = PV_SMEM_BYTES;                       // 54784

    cudaFuncSetAttribute((const void*)gemm_wmma<128, 2, 4>,
                         cudaFuncAttributeMaxDynamicSharedMemorySize, SM_G128);
    cudaFuncSetAttribute((const void*)gemm_wmma<32, 8, 1>,
                         cudaFuncAttributeMaxDynamicSharedMemorySize, SM_G32);
    cudaFuncSetAttribute((const void*)logits_exp_wmma,
                         cudaFuncAttributeMaxDynamicSharedMemorySize, SM_LOG);
    cudaFuncSetAttribute((const void*)pv_wmma,
                         cudaFuncAttributeMaxDynamicSharedMemorySize, SM_PV);

    dim3 gProj(DA_ / 128, BS_ / 128);   // (4, 64)

    // projections (tf32 WMMA, pipelined)
    gemm_wmma<128, 2, 4><<<gProj, 256, SM_G128>>>(q, wq, bq, qp, BS_, DA_, DM_);
    gemm_wmma<128, 2, 4><<<gProj, 256, SM_G128>>>(k, wk, bk, kp, BS_, DA_, DM_);
    gemm_wmma<128, 2, 4><<<gProj, 256, SM_G128>>>(v, wv, bv, vp, BS_, DA_, DM_);

    // x = qp @ wx + bx
    gemm_wmma<32, 8, 1><<<dim3(1, BS_ / 128), 256, SM_G32>>>(qp, wx, bx, xs,
                                                             BS_, H_ * F_, DA_);

    // logits + bias + exp -> attn (unnormalized) + partial sums
    logits_exp_wmma<<<dim3(S_ / 32, S_ / 64, B_), 256, SM_LOG>>>(
        qp, kp, xs, xdiff, attn, psum);

    // rowsum -> 1/s
    rowsum_kernel<<<ROWS_ / 8, 256>>>(psum, rinv);

    // PV + in-place normalization of attn
    pv_wmma<<<dim3(S_ / 128, B_ * H_), 256, SM_PV>>>(attn, vp, rinv, ctx);

    // out = ctx @ wo + bo
    gemm_wmma<128, 2, 4><<<gProj, 256, SM_G128>>>(ctx, wo, bo, out, BS_, DM_, DA_);
}

// round 10
// speedup vs baseline: 1.5156x; 1.0300x over previous
#include <cuda_runtime.h>
#include <mma.h>
#include <cstdint>
#include <cstddef>

using namespace nvcuda;

// Problem dims
#define B_ 4
#define S_ 2048
#define DM_ 512
#define DA_ 512
#define H_ 8
#define F_ 4
#define DEP_ 64
#define BS_ (B_ * S_)         // 8192
#define ROWS_ (B_ * H_ * S_)  // 65536

// ---------------- scratch (no allocations allowed) ----------------
__device__ float g_qp[(size_t)BS_ * DA_];
__device__ float g_kp[(size_t)BS_ * DA_];
__device__ float g_vp[(size_t)BS_ * DA_];
__device__ float g_xs[(size_t)BS_ * (H_ * F_)];
__device__ float g_ctx[(size_t)BS_ * DA_];
__device__ float g_psum[(size_t)ROWS_ * 128];
__device__ float g_rinv[(size_t)ROWS_];

typedef wmma::fragment<wmma::matrix_a, 16, 16, 8, wmma::precision::tf32, wmma::row_major> FragA;
typedef wmma::fragment<wmma::matrix_b, 16, 16, 8, wmma::precision::tf32, wmma::row_major> FragB;
typedef wmma::fragment<wmma::matrix_b, 16, 16, 8, wmma::precision::tf32, wmma::col_major> FragBc;
typedef wmma::fragment<wmma::accumulator, 16, 16, 8, float> FragC;

template <typename F>
__device__ __forceinline__ void cvt_tf32(F& f) {
#pragma unroll
    for (int i = 0; i < f.num_elements; i++)
        f.x[i] = wmma::__float_to_tf32(f.x[i]);
}

// ---------------- cp.async helpers ----------------
__device__ __forceinline__ void cp16(float* dst_smem, const float* src_g) {
    uint32_t d = (uint32_t)__cvta_generic_to_shared(dst_smem);
    asm volatile("cp.async.cg.shared.global [%0], [%1], 16;"
                 :: "r"(d), "l"(src_g) : "memory");
}
__device__ __forceinline__ void cp_commit() {
    asm volatile("cp.async.commit_group;" ::: "memory");
}
template <int N>
__device__ __forceinline__ void cp_wait() {
    asm volatile("cp.async.wait_group %0;" :: "n"(N) : "memory");
}

// =================================================================
// WMMA tf32 GEMM, 3-stage cp.async ring.
// C[M,N] = A[M,K] @ W[K,N] + bias[N]; block tile 128 x BN, BK=32.
// =================================================================
template <int BN, int WR, int WC>
__global__ __launch_bounds__(256) void gemm_wmma(
    const float* __restrict__ A, const float* __restrict__ W,
    const float* __restrict__ bias, float* __restrict__ C,
    int M, int N, int K)
{
    constexpr int LDA = 36;
    constexpr int LDB = BN + 4;
    constexpr int SA  = 128 * LDA;
    constexpr int SW  = 32 * LDB;
    constexpr int MI = 128 / (WR * 16);
    constexpr int NI = BN / (WC * 16);

    extern __shared__ float sm[];
    float* Cs = sm;

    const int tid = threadIdx.x;
    const int wid = tid >> 5;
    const int warp_m = wid % WR;
    const int warp_n = wid / WR;
    const int m0 = blockIdx.y * 128;
    const int n0 = blockIdx.x * BN;
    const int nc = K / 32;

    auto loadStage = [&](int st, int c) {
        float* As = sm + st * SA;
        float* Ws = sm + 3 * SA + st * SW;
#pragma unroll
        for (int r = 0; r < 4; r++) {
            int idx = tid + 256 * r;
            int m = idx >> 3, k4 = (idx & 7) * 4;
            cp16(&As[m * LDA + k4], &A[(size_t)(m0 + m) * K + c * 32 + k4]);
        }
#pragma unroll
        for (int r = 0; r < BN / 32; r++) {
            int idx = tid + 256 * r;
            int kk = idx / (BN / 4), n4 = (idx % (BN / 4)) * 4;
            cp16(&Ws[kk * LDB + n4], &W[(size_t)(c * 32 + kk) * N + n0 + n4]);
        }
    };

    FragC acc[MI][NI];
#pragma unroll
    for (int i = 0; i < MI; i++)
#pragma unroll
        for (int j = 0; j < NI; j++) wmma::fill_fragment(acc[i][j], 0.0f);

    loadStage(0, 0); cp_commit();
    loadStage(1, 1); cp_commit();

    for (int c = 0; c < nc; c++) {
        if (c + 2 < nc) {
            loadStage((c + 2) % 3, c + 2);
            cp_commit();
            cp_wait<2>();
        } else if (c + 1 < nc) {
            cp_wait<1>();
        } else {
            cp_wait<0>();
        }
        __syncthreads();

        const float* As = sm + (c % 3) * SA;
        const float* Ws = sm + 3 * SA + (c % 3) * SW;
#pragma unroll
        for (int ds = 0; ds < 4; ds++) {
            FragA af[MI];
#pragma unroll
            for (int i = 0; i < MI; i++) {
                wmma::load_matrix_sync(af[i],
                    &As[(warp_m * (128 / WR) + i * 16) * LDA + ds * 8], LDA);
                cvt_tf32(af[i]);
            }
            FragB bf;
#pragma unroll
            for (int j = 0; j < NI; j++) {
                wmma::load_matrix_sync(bf,
                    &Ws[ds * 8 * LDB + warp_n * (BN / WC) + j * 16], LDB);
                cvt_tf32(bf);
#pragma unroll
                for (int i = 0; i < MI; i++)
                    wmma::mma_sync(acc[i][j], af[i], bf, acc[i][j]);
            }
        }
        __syncthreads();
    }

    // epilogue
#pragma unroll
    for (int i = 0; i < MI; i++)
#pragma unroll
        for (int j = 0; j < NI; j++)
            wmma::store_matrix_sync(
                &Cs[(warp_m * (128 / WR) + i * 16) * LDB +
                    warp_n * (BN / WC) + j * 16],
                acc[i][j], LDB, wmma::mem_row_major);
    __syncthreads();

#pragma unroll
    for (int r = 0; r < BN / 8; r++) {
        int idx = tid + 256 * r;
        int m = idx / (BN / 4), n4 = (idx % (BN / 4)) * 4;
        float4 v = *(float4*)&Cs[m * LDB + n4];
        float4 bz = *(const float4*)&bias[n0 + n4];
        v.x += bz.x; v.y += bz.y; v.z += bz.z; v.w += bz.w;
        *(float4*)&C[(size_t)(m0 + m) * N + n0 + n4] = v;
    }
}

// =================================================================
// Logits+exp, pipelined across heads, private per-warp epilogue bufs.
// Block = (b, 64q, 32k); xdiff tile read from HBM exactly once.
// smem: Qt[2][64*68] Kt[2][32*68] xw[2048] xd f4[64][33] Ls[8][16*20]
// = 104448 B -> 2 blocks/SM. 2 syncthreads per head.
// =================================================================
#define LOG_SMEM_BYTES 104448

__global__ __launch_bounds__(256) void logits_exp_wmma(
    const float* __restrict__ qp, const float* __restrict__ kp,
    const float* __restrict__ xs, const float* __restrict__ xdiff,
    float* __restrict__ attn, float* __restrict__ psum)
{
    constexpr int SQ = 64 * 68;   // 4352
    constexpr int SK = 32 * 68;   // 2176

    extern __shared__ float sm[];
    float*  QtB = sm;                        // 2 stages
    float*  KtB = sm + 2 * SQ;               // 2 stages
    float*  xw  = sm + 2 * SQ + 2 * SK;      // 2048
    float4* xd  = (float4*)(xw + 2048);      // [64][33] f4 (8448 floats)
    float*  LsB = xw + 2048 + 8448;          // [8][16*20] = 2560 floats

    const int tid  = threadIdx.x;
    const int w    = tid >> 5;
    const int lane = tid & 31;
    const int wq   = w & 3;     // q-group (16 rows)
    const int wkh  = w >> 2;    // k-half (16 cols)
    const int b  = blockIdx.z;
    const int q0 = blockIdx.y * 64;
    const int k0 = blockIdx.x * 32;
    float* Ls = LsB + w * 320;  // private 16x20

    auto loadQK = [&](int st, int h) {
        float* Qt = QtB + st * SQ;
        float* Kt = KtB + st * SK;
#pragma unroll
        for (int r = 0; r < 4; r++) {
            int idx = tid + 256 * r;
            int qi = idx >> 4, d4 = (idx & 15) * 4;
            cp16(&Qt[qi * 68 + d4],
                 &qp[(size_t)(b * S_ + q0 + qi) * DA_ + h * DEP_ + d4]);
        }
#pragma unroll
        for (int r = 0; r < 2; r++) {
            int idx = tid + 256 * r;
            int kk = idx >> 4, d4 = (idx & 15) * 4;
            cp16(&Kt[kk * 68 + d4],
                 &kp[(size_t)(b * S_ + k0 + kk) * DA_ + h * DEP_ + d4]);
        }
    };

    // one-time tiles (group 0, together with head 0)
    {
        const float4* xdg = (const float4*)xdiff;
#pragma unroll
        for (int r = 0; r < 8; r++) {
            int idx = tid + 256 * r;
            int qi = idx >> 5, kj = idx & 31;
            cp16((float*)&xd[qi * 33 + kj],
                 (const float*)&xdg[((size_t)(b * S_ + q0 + qi)) * S_ + k0 + kj]);
        }
#pragma unroll
        for (int r = 0; r < 2; r++) {
            int idx = tid + 256 * r;
            int qi = idx >> 3, c4 = (idx & 7) * 4;
            cp16(&xw[qi * 32 + c4],
                 &xs[(size_t)(b * S_ + q0 + qi) * 32 + c4]);
        }
    }
    loadQK(0, 0);
    cp_commit();

    for (int h = 0; h < H_; h++) {
        if (h) __syncthreads();          // MMA(h-1) reads done before cp reuse
        if (h + 1 < H_) {
            loadQK((h + 1) & 1, h + 1);  // overwrites stage (h-1)&1
            cp_commit();
            cp_wait<1>();
        } else {
            cp_wait<0>();
        }
        __syncthreads();                 // stage h visible to all warps

        float* Qt = QtB + (h & 1) * SQ;
        float* Kt = KtB + (h & 1) * SK;

        FragC acc;
        wmma::fill_fragment(acc, 0.0f);
#pragma unroll
        for (int ds = 0; ds < 8; ds++) {
            FragA a;
            wmma::load_matrix_sync(a, &Qt[(wq * 16) * 68 + ds * 8], 68);
            cvt_tf32(a);
            FragBc bf;
            wmma::load_matrix_sync(bf, &Kt[(wkh * 16) * 68 + ds * 8], 68);
            cvt_tf32(bf);
            wmma::mma_sync(acc, a, bf, acc);
        }

        // private epilogue buffer — no cross-warp dependency
        wmma::store_matrix_sync(Ls, acc, 20, wmma::mem_row_major);
        __syncwarp();

#pragma unroll
        for (int r = 0; r < 2; r++) {
            int idx = lane + 32 * r;        // 0..63 = 16 rows x 4 f4
            int qi = idx >> 2;              // 0..15
            int g  = idx & 3;               // f4 group within 16-col half
            int qrow = wq * 16 + qi;
            int fcol = wkh * 16 + g * 4;    // global col in 32-wide tile
            float4 lv = *(float4*)&Ls[qi * 20 + g * 4];
            float4 xh = *(float4*)&xw[qrow * 32 + h * 4];
            float e[4];
            float* lp = &lv.x;
            float tsum = 0.0f;
#pragma unroll
            for (int t = 0; t < 4; t++) {
                float4 xv = xd[qrow * 33 + fcol + t];
                float bias = xv.x * xh.x + xv.y * xh.y + xv.z * xh.z + xv.w * xh.w;
                e[t] = __expf(lp[t] * 0.125f + bias * 0.5f);
                tsum += e[t];
            }
            size_t row_g = (size_t)(b * H_ + h) * S_ + q0 + qrow;
            *(float4*)&attn[row_g * S_ + k0 + fcol] =
                make_float4(e[0], e[1], e[2], e[3]);
            tsum += __shfl_down_sync(0xffffffffu, tsum, 2, 4);
            tsum += __shfl_down_sync(0xffffffffu, tsum, 1, 4);
            if ((lane & 3) == 0)
                psum[row_g * 128 + blockIdx.x * 2 + wkh] = tsum;
        }
    }
}

// =================================================================
// Row-sum reduce: g_rinv[row] = 1 / sum(g_psum[row][0..127])
// =================================================================
__global__ __launch_bounds__(256) void rowsum_kernel(
    const float* __restrict__ psum, float* __restrict__ rinv)
{
    const int wir  = threadIdx.x >> 5;
    const int lane = threadIdx.x & 31;
    const size_t row = (size_t)blockIdx.x * 8 + wir;
    const float* p = psum + row * 128;
    float s = (p[lane] + p[lane + 32]) + (p[lane + 64] + p[lane + 96]);
#pragma unroll
    for (int o = 16; o > 0; o >>= 1) s += __shfl_xor_sync(0xffffffffu, s, o);
    if (lane == 0) rinv[row] = 1.0f / s;
}

// =================================================================
// PV, 3-stage ring, 64q tiles: ctx = (e @ V) * rinv ; writes
// p = e*rinv back to attn in place. Block = (64q, bh), BK=32.
// smem: At[3][64*36] Vt[3][32*68] rs[64] = 54016 B -> 4 blocks/SM.
// =================================================================
#define PV_SMEM_BYTES 54016

__global__ __launch_bounds__(256) void pv_wmma(
    float* __restrict__ attn, const float* __restrict__ vp,
    const float* __restrict__ rinv, float* __restrict__ ctx)
{
    constexpr int SA = 64 * 36;   // 2304
    constexpr int SV = 32 * 68;   // 2176

    extern __shared__ float sm[];
    float* AtB = sm;
    float* VtB = sm + 3 * SA;
    float* rs  = sm + 3 * SA + 3 * SV;   // [64]
    float* Cs  = sm;                     // epilogue reuse (64*68 <= 3*SA)

    const int tid = threadIdx.x;
    const int w   = tid >> 5;
    const int wq  = w & 3;    // q-group (16 rows)
    const int wd  = w >> 2;   // d-half (32 cols)
    const int bh  = blockIdx.y;
    const int b   = bh >> 3, h = bh & 7;
    const int q0  = blockIdx.x * 64;
    const int nc  = S_ / 32;  // 64

    if (tid < 64) rs[tid] = rinv[(size_t)bh * S_ + q0 + tid];

    auto loadChunk = [&](int st, int c) {
        float* At = AtB + st * SA;
        float* Vt = VtB + st * SV;
#pragma unroll
        for (int r = 0; r < 2; r++) {
            int idx = tid + 256 * r;
            int qi = idx >> 3, k4 = (idx & 7) * 4;
            cp16(&At[qi * 36 + k4],
                 &attn[((size_t)bh * S_ + q0 + qi) * S_ + c * 32 + k4]);
        }
#pragma unroll
        for (int r = 0; r < 2; r++) {
            int idx = tid + 256 * r;
            int kk = idx >> 4, d4 = (idx & 15) * 4;
            cp16(&Vt[kk * 68 + d4],
                 &vp[(size_t)(b * S_ + c * 32 + kk) * DA_ + h * DEP_ + d4]);
        }
    };

    FragC acc[2];
#pragma unroll
    for (int j = 0; j < 2; j++) wmma::fill_fragment(acc[j], 0.0f);

    loadChunk(0, 0); cp_commit();
    loadChunk(1, 1); cp_commit();

    for (int c = 0; c < nc; c++) {
        if (c + 2 < nc) {
            loadChunk((c + 2) % 3, c + 2);
            cp_commit();
            cp_wait<2>();
        } else if (c + 1 < nc) {
            cp_wait<1>();
        } else {
            cp_wait<0>();
        }
        __syncthreads();

        const float* At = AtB + (c % 3) * SA;
        const float* Vt = VtB + (c % 3) * SV;

        // write p = e * rinv back to attn (raw e stays in smem for MMA)
#pragma unroll
        for (int r = 0; r < 2; r++) {
            int idx = tid + 256 * r;
            int qi = idx >> 3, k4 = (idx & 7) * 4;
            float4 v = *(const float4*)&At[qi * 36 + k4];
            float riv = rs[qi];
            v.x *= riv; v.y *= riv; v.z *= riv; v.w *= riv;
            *(float4*)&attn[((size_t)bh * S_ + q0 + qi) * S_ + c * 32 + k4] = v;
        }

#pragma unroll
        for (int ds = 0; ds < 4; ds++) {
            FragA a;
            wmma::load_matrix_sync(a, &At[(wq * 16) * 36 + ds * 8], 36);
            cvt_tf32(a);
#pragma unroll
            for (int j = 0; j < 2; j++) {
                FragB bf;
                wmma::load_matrix_sync(bf, &Vt[ds * 8 * 68 + wd * 32 + j * 16], 68);
                cvt_tf32(bf);
                wmma::mma_sync(acc[j], a, bf, acc[j]);
            }
        }
        __syncthreads();
    }

    // epilogue: stage in smem, scale by rinv, store
#pragma unroll
    for (int j = 0; j < 2; j++)
        wmma::store_matrix_sync(&Cs[(wq * 16) * 68 + wd * 32 + j * 16],
                                acc[j], 68, wmma::mem_row_major);
    __syncthreads();

#pragma unroll
    for (int r = 0; r < 4; r++) {
        int idx = tid + 256 * r;
        int qi = idx >> 4, d4 = (idx & 15) * 4;
        float4 v = *(float4*)&Cs[qi * 68 + d4];
        float riv = rs[qi];
        v.x *= riv; v.y *= riv; v.z *= riv; v.w *= riv;
        *(float4*)&ctx[(size_t)(b * S_ + q0 + qi) * DA_ + h * DEP_ + d4] = v;
    }
}

// =================================================================
extern "C" void kernel_launch(void* const* d_in, const int* in_sizes, int n_in,
                              void* d_out, int out_size)
{
    const float* q     = (const float*)d_in[0];
    const float* k     = (const float*)d_in[1];
    const float* v     = (const float*)d_in[2];
    const float* xdiff = (const float*)d_in[3];
    const float* wq    = (const float*)d_in[4];
    const float* bq    = (const float*)d_in[5];
    const float* wk    = (const float*)d_in[6];
    const float* bk    = (const float*)d_in[7];
    const float* wv    = (const float*)d_in[8];
    const float* bv    = (const float*)d_in[9];
    const float* wx    = (const float*)d_in[10];
    const float* bx    = (const float*)d_in[11];
    const float* wo    = (const float*)d_in[12];
    const float* bo    = (const float*)d_in[13];

    float* out  = (float*)d_out;                        // [B,S,DM]
    float* attn = out + (size_t)BS_ * DM_;              // [B,H,S,S]

    float *qp, *kp, *vp, *xs, *ctx, *psum, *rinv;
    cudaGetSymbolAddress((void**)&qp,   g_qp);
    cudaGetSymbolAddress((void**)&kp,   g_kp);
    cudaGetSymbolAddress((void**)&vp,   g_vp);
    cudaGetSymbolAddress((void**)&xs,   g_xs);
    cudaGetSymbolAddress((void**)&ctx,  g_ctx);
    cudaGetSymbolAddress((void**)&psum, g_psum);
    cudaGetSymbolAddress((void**)&rinv, g_rinv);

    const int SM_G128 = (3 * 128 * 36 + 3 * 32 * 132) * 4;   // 105984
    const int SM_G32  = (3 * 128 * 36 + 3 * 32 * 36) * 4;    // 69120
    const int SM_LOG  = LOG_SMEM_BYTES;                      // 104448
    const int SM_PV   = PV_SMEM_BYTES;                       // 54016

    cudaFuncSetAttribute((const void*)gemm_wmma<128, 2, 4>,
                         cudaFuncAttributeMaxDynamicSharedMemorySize, SM_G128);
    cudaFuncSetAttribute((const void*)gemm_wmma<32, 8, 1>,
                         cudaFuncAttributeMaxDynamicSharedMemorySize, SM_G32);
    cudaFuncSetAttribute((const void*)logits_exp_wmma,
                         cudaFuncAttributeMaxDynamicSharedMemorySize, SM_LOG);
    cudaFuncSetAttribute((const void*)pv_wmma,
                         cudaFuncAttributeMaxDynamicSharedMemorySize, SM_PV);

    dim3 gProj(DA_ / 128, BS_ / 128);   // (4, 64)

    // projections (tf32 WMMA, 3-stage pipelined)
    gemm_wmma<128, 2, 4><<<gProj, 256, SM_G128>>>(q, wq, bq, qp, BS_, DA_, DM_);
    gemm_wmma<128, 2, 4><<<gProj, 256, SM_G128>>>(k, wk, bk, kp, BS_, DA_, DM_);
    gemm_wmma<128, 2, 4><<<gProj, 256, SM_G128>>>(v, wv, bv, vp, BS_, DA_, DM_);

    // x = qp @ wx + bx
    gemm_wmma<32, 8, 1><<<dim3(1, BS_ / 128), 256, SM_G32>>>(qp, wx, bx, xs,
                                                             BS_, H_ * F_, DA_);

    // logits + bias + exp -> attn (unnormalized) + partial sums
    logits_exp_wmma<<<dim3(S_ / 32, S_ / 64, B_), 256, SM_LOG>>>(
        qp, kp, xs, xdiff, attn, psum);

    // rowsum -> 1/s
    rowsum_kernel<<<ROWS_ / 8, 256>>>(psum, rinv);

    // PV + in-place normalization of attn
    pv_wmma<<<dim3(S_ / 64, B_ * H_), 256, SM_PV>>>(attn, vp, rinv, ctx);

    // out = ctx @ wo + bo
    gemm_wmma<128, 2, 4><<<gProj, 256, SM_G128>>>(ctx, wo, bo, out, BS_, DM_, DA_);
}

// round 11
// speedup vs baseline: 1.6269x; 1.0735x over previous
#include <cuda_runtime.h>
#include <mma.h>
#include <cstdint>
#include <cstddef>

using namespace nvcuda;

// Problem dims
#define B_ 4
#define S_ 2048
#define DM_ 512
#define DA_ 512
#define H_ 8
#define F_ 4
#define DEP_ 64
#define BS_ (B_ * S_)         // 8192
#define ROWS_ (B_ * H_ * S_)  // 65536

// ---------------- scratch (no allocations allowed) ----------------
__device__ float g_qp[(size_t)BS_ * DA_];
__device__ float g_kp[(size_t)BS_ * DA_];
__device__ float g_vp[(size_t)BS_ * DA_];
__device__ float g_xs[(size_t)BS_ * (H_ * F_)];
__device__ float g_ctx[(size_t)BS_ * DA_];
__device__ float g_psum[(size_t)ROWS_ * 128];
__device__ float g_rinv[(size_t)ROWS_];

typedef wmma::fragment<wmma::matrix_a, 16, 16, 8, wmma::precision::tf32, wmma::row_major> FragA;
typedef wmma::fragment<wmma::matrix_b, 16, 16, 8, wmma::precision::tf32, wmma::row_major> FragB;
typedef wmma::fragment<wmma::matrix_b, 16, 16, 8, wmma::precision::tf32, wmma::col_major> FragBc;
typedef wmma::fragment<wmma::accumulator, 16, 16, 8, float> FragC;

template <typename F>
__device__ __forceinline__ void cvt_tf32(F& f) {
#pragma unroll
    for (int i = 0; i < f.num_elements; i++)
        f.x[i] = wmma::__float_to_tf32(f.x[i]);
}

// ---------------- cp.async helpers ----------------
__device__ __forceinline__ void cp16(float* dst_smem, const float* src_g) {
    uint32_t d = (uint32_t)__cvta_generic_to_shared(dst_smem);
    asm volatile("cp.async.cg.shared.global [%0], [%1], 16;"
                 :: "r"(d), "l"(src_g) : "memory");
}
__device__ __forceinline__ void cp_commit() {
    asm volatile("cp.async.commit_group;" ::: "memory");
}
template <int N>
__device__ __forceinline__ void cp_wait() {
    asm volatile("cp.async.wait_group %0;" :: "n"(N) : "memory");
}

// =================================================================
// WMMA tf32 GEMM, 3-stage cp.async ring.
// C[M,N] = A[M,K] @ W[K,N] + bias[N]; block tile BM x BN, BK=32.
// =================================================================
template <int BM, int BN, int WR, int WC>
__global__ __launch_bounds__(256) void gemm_wmma(
    const float* __restrict__ A, const float* __restrict__ W,
    const float* __restrict__ bias, float* __restrict__ C,
    int M, int N, int K)
{
    constexpr int LDA = 36;
    constexpr int LDB = BN + 4;
    constexpr int SA  = BM * LDA;
    constexpr int SW  = 32 * LDB;
    constexpr int MI = BM / (WR * 16);
    constexpr int NI = BN / (WC * 16);

    extern __shared__ float sm[];
    float* Cs = sm;

    const int tid = threadIdx.x;
    const int wid = tid >> 5;
    const int warp_m = wid % WR;
    const int warp_n = wid / WR;
    const int m0 = blockIdx.y * BM;
    const int n0 = blockIdx.x * BN;
    const int nc = K / 32;

    auto loadStage = [&](int st, int c) {
        float* As = sm + st * SA;
        float* Ws = sm + 3 * SA + st * SW;
#pragma unroll
        for (int r = 0; r < BM / 32; r++) {
            int idx = tid + 256 * r;
            int m = idx >> 3, k4 = (idx & 7) * 4;
            cp16(&As[m * LDA + k4], &A[(size_t)(m0 + m) * K + c * 32 + k4]);
        }
#pragma unroll
        for (int r = 0; r < BN / 32; r++) {
            int idx = tid + 256 * r;
            int kk = idx / (BN / 4), n4 = (idx % (BN / 4)) * 4;
            cp16(&Ws[kk * LDB + n4], &W[(size_t)(c * 32 + kk) * N + n0 + n4]);
        }
    };

    FragC acc[MI][NI];
#pragma unroll
    for (int i = 0; i < MI; i++)
#pragma unroll
        for (int j = 0; j < NI; j++) wmma::fill_fragment(acc[i][j], 0.0f);

    loadStage(0, 0); cp_commit();
    loadStage(1, 1); cp_commit();

    for (int c = 0; c < nc; c++) {
        if (c + 2 < nc) {
            loadStage((c + 2) % 3, c + 2);
            cp_commit();
            cp_wait<2>();
        } else if (c + 1 < nc) {
            cp_wait<1>();
        } else {
            cp_wait<0>();
        }
        __syncthreads();

        const float* As = sm + (c % 3) * SA;
        const float* Ws = sm + 3 * SA + (c % 3) * SW;
#pragma unroll
        for (int ds = 0; ds < 4; ds++) {
            FragA af[MI];
#pragma unroll
            for (int i = 0; i < MI; i++) {
                wmma::load_matrix_sync(af[i],
                    &As[(warp_m * (BM / WR) + i * 16) * LDA + ds * 8], LDA);
                cvt_tf32(af[i]);
            }
            FragB bf;
#pragma unroll
            for (int j = 0; j < NI; j++) {
                wmma::load_matrix_sync(bf,
                    &Ws[ds * 8 * LDB + warp_n * (BN / WC) + j * 16], LDB);
                cvt_tf32(bf);
#pragma unroll
                for (int i = 0; i < MI; i++)
                    wmma::mma_sync(acc[i][j], af[i], bf, acc[i][j]);
            }
        }
        __syncthreads();
    }

    // epilogue
#pragma unroll
    for (int i = 0; i < MI; i++)
#pragma unroll
        for (int j = 0; j < NI; j++)
            wmma::store_matrix_sync(
                &Cs[(warp_m * (BM / WR) + i * 16) * LDB +
                    warp_n * (BN / WC) + j * 16],
                acc[i][j], LDB, wmma::mem_row_major);
    __syncthreads();

#pragma unroll
    for (int r = 0; r < BM * BN / 1024; r++) {
        int idx = tid + 256 * r;
        int m = idx / (BN / 4), n4 = (idx % (BN / 4)) * 4;
        float4 v = *(float4*)&Cs[m * LDB + n4];
        float4 bz = *(const float4*)&bias[n0 + n4];
        v.x += bz.x; v.y += bz.y; v.z += bz.z; v.w += bz.w;
        *(float4*)&C[(size_t)(m0 + m) * N + n0 + n4] = v;
    }
}

// =================================================================
// Logits+exp, pipelined across heads; xdiff lives in REGISTERS
// (per-thread mapping is head-invariant -> loaded once from global).
// Block = (b, 64q, 32k).
// smem: Qt[2][64*68] Kt[2][32*68] xw[2048] Ls[8][16*20] = 70656 B.
// =================================================================
#define LOG_SMEM_BYTES 70656

__global__ __launch_bounds__(256) void logits_exp_wmma(
    const float* __restrict__ qp, const float* __restrict__ kp,
    const float* __restrict__ xs, const float* __restrict__ xdiff,
    float* __restrict__ attn, float* __restrict__ psum)
{
    constexpr int SQ = 64 * 68;   // 4352
    constexpr int SK = 32 * 68;   // 2176

    extern __shared__ float sm[];
    float* QtB = sm;                     // 2 stages
    float* KtB = sm + 2 * SQ;            // 2 stages
    float* xw  = sm + 2 * SQ + 2 * SK;   // 2048
    float* LsB = xw + 2048;              // 8 x 320

    const int tid  = threadIdx.x;
    const int w    = tid >> 5;
    const int lane = tid & 31;
    const int wq   = w & 3;     // q-group (16 rows)
    const int wkh  = w >> 2;    // k-half (16 cols)
    const int b  = blockIdx.z;
    const int q0 = blockIdx.y * 64;
    const int k0 = blockIdx.x * 32;
    float* Ls = LsB + w * 320;  // private 16x20

    auto loadQK = [&](int st, int h) {
        float* Qt = QtB + st * SQ;
        float* Kt = KtB + st * SK;
#pragma unroll
        for (int r = 0; r < 4; r++) {
            int idx = tid + 256 * r;
            int qi = idx >> 4, d4 = (idx & 15) * 4;
            cp16(&Qt[qi * 68 + d4],
                 &qp[(size_t)(b * S_ + q0 + qi) * DA_ + h * DEP_ + d4]);
        }
#pragma unroll
        for (int r = 0; r < 2; r++) {
            int idx = tid + 256 * r;
            int kk = idx >> 4, d4 = (idx & 15) * 4;
            cp16(&Kt[kk * 68 + d4],
                 &kp[(size_t)(b * S_ + k0 + kk) * DA_ + h * DEP_ + d4]);
        }
    };

    // xw tile (one-time, via cp.async alongside head 0)
#pragma unroll
    for (int r = 0; r < 2; r++) {
        int idx = tid + 256 * r;
        int qi = idx >> 3, c4 = (idx & 7) * 4;
        cp16(&xw[qi * 32 + c4], &xs[(size_t)(b * S_ + q0 + qi) * 32 + c4]);
    }
    loadQK(0, 0);
    cp_commit();

    // xdiff -> registers: thread's epilogue elements are head-invariant.
    // For r in {0,1}: qi=(lane+32r)>>2, g=(lane+32r)&3;
    // row = q0 + wq*16 + qi, f4 col = k0 + wkh*16 + g*4 (+0..3)
    float4 xdr[2][4];
    const float4* xdg = (const float4*)xdiff;
#pragma unroll
    for (int r = 0; r < 2; r++) {
        int idx = lane + 32 * r;
        int qi = idx >> 2, g = idx & 3;
        int qrow = wq * 16 + qi;
        int fcol = wkh * 16 + g * 4;
        const float4* src = &xdg[((size_t)(b * S_ + q0 + qrow)) * S_ + k0 + fcol];
#pragma unroll
        for (int t = 0; t < 4; t++) xdr[r][t] = src[t];
    }

    for (int h = 0; h < H_; h++) {
        if (h) __syncthreads();          // MMA(h-1) reads done before cp reuse
        if (h + 1 < H_) {
            loadQK((h + 1) & 1, h + 1);
            cp_commit();
            cp_wait<1>();
        } else {
            cp_wait<0>();
        }
        __syncthreads();                 // stage h visible

        float* Qt = QtB + (h & 1) * SQ;
        float* Kt = KtB + (h & 1) * SK;

        FragC acc;
        wmma::fill_fragment(acc, 0.0f);
#pragma unroll
        for (int ds = 0; ds < 8; ds++) {
            FragA a;
            wmma::load_matrix_sync(a, &Qt[(wq * 16) * 68 + ds * 8], 68);
            cvt_tf32(a);
            FragBc bf;
            wmma::load_matrix_sync(bf, &Kt[(wkh * 16) * 68 + ds * 8], 68);
            cvt_tf32(bf);
            wmma::mma_sync(acc, a, bf, acc);
        }

        wmma::store_matrix_sync(Ls, acc, 20, wmma::mem_row_major);
        __syncwarp();

#pragma unroll
        for (int r = 0; r < 2; r++) {
            int idx = lane + 32 * r;
            int qi = idx >> 2;
            int g  = idx & 3;
            int qrow = wq * 16 + qi;
            int fcol = wkh * 16 + g * 4;
            float4 lv = *(float4*)&Ls[qi * 20 + g * 4];
            float4 xh = *(float4*)&xw[qrow * 32 + h * 4];
            float e[4];
            float* lp = &lv.x;
            float tsum = 0.0f;
#pragma unroll
            for (int t = 0; t < 4; t++) {
                float4 xv = xdr[r][t];
                float bias = xv.x * xh.x + xv.y * xh.y + xv.z * xh.z + xv.w * xh.w;
                e[t] = __expf(lp[t] * 0.125f + bias * 0.5f);
                tsum += e[t];
            }
            size_t row_g = (size_t)(b * H_ + h) * S_ + q0 + qrow;
            *(float4*)&attn[row_g * S_ + k0 + fcol] =
                make_float4(e[0], e[1], e[2], e[3]);
            tsum += __shfl_down_sync(0xffffffffu, tsum, 2, 4);
            tsum += __shfl_down_sync(0xffffffffu, tsum, 1, 4);
            if ((lane & 3) == 0)
                psum[row_g * 128 + blockIdx.x * 2 + wkh] = tsum;
        }
    }
}

// =================================================================
// Row-sum reduce: g_rinv[row] = 1 / sum(g_psum[row][0..127])
// =================================================================
__global__ __launch_bounds__(256) void rowsum_kernel(
    const float* __restrict__ psum, float* __restrict__ rinv)
{
    const int wir  = threadIdx.x >> 5;
    const int lane = threadIdx.x & 31;
    const size_t row = (size_t)blockIdx.x * 8 + wir;
    const float* p = psum + row * 128;
    float s = (p[lane] + p[lane + 32]) + (p[lane + 64] + p[lane + 96]);
#pragma unroll
    for (int o = 16; o > 0; o >>= 1) s += __shfl_xor_sync(0xffffffffu, s, o);
    if (lane == 0) rinv[row] = 1.0f / s;
}

// =================================================================
// PV, 3-stage ring, 64q tiles: ctx = (e @ V) * rinv ; writes
// p = e*rinv back to attn in place. Block = (64q, bh), BK=32.
// =================================================================
#define PV_SMEM_BYTES 54016

__global__ __launch_bounds__(256) void pv_wmma(
    float* __restrict__ attn, const float* __restrict__ vp,
    const float* __restrict__ rinv, float* __restrict__ ctx)
{
    constexpr int SA = 64 * 36;   // 2304
    constexpr int SV = 32 * 68;   // 2176

    extern __shared__ float sm[];
    float* AtB = sm;
    float* VtB = sm + 3 * SA;
    float* rs  = sm + 3 * SA + 3 * SV;   // [64]
    float* Cs  = sm;                     // epilogue reuse

    const int tid = threadIdx.x;
    const int w   = tid >> 5;
    const int wq  = w & 3;
    const int wd  = w >> 2;
    const int bh  = blockIdx.y;
    const int b   = bh >> 3, h = bh & 7;
    const int q0  = blockIdx.x * 64;
    const int nc  = S_ / 32;

    if (tid < 64) rs[tid] = rinv[(size_t)bh * S_ + q0 + tid];

    auto loadChunk = [&](int st, int c) {
        float* At = AtB + st * SA;
        float* Vt = VtB + st * SV;
#pragma unroll
        for (int r = 0; r < 2; r++) {
            int idx = tid + 256 * r;
            int qi = idx >> 3, k4 = (idx & 7) * 4;
            cp16(&At[qi * 36 + k4],
                 &attn[((size_t)bh * S_ + q0 + qi) * S_ + c * 32 + k4]);
        }
#pragma unroll
        for (int r = 0; r < 2; r++) {
            int idx = tid + 256 * r;
            int kk = idx >> 4, d4 = (idx & 15) * 4;
            cp16(&Vt[kk * 68 + d4],
                 &vp[(size_t)(b * S_ + c * 32 + kk) * DA_ + h * DEP_ + d4]);
        }
    };

    FragC acc[2];
#pragma unroll
    for (int j = 0; j < 2; j++) wmma::fill_fragment(acc[j], 0.0f);

    loadChunk(0, 0); cp_commit();
    loadChunk(1, 1); cp_commit();

    for (int c = 0; c < nc; c++) {
        if (c + 2 < nc) {
            loadChunk((c + 2) % 3, c + 2);
            cp_commit();
            cp_wait<2>();
        } else if (c + 1 < nc) {
            cp_wait<1>();
        } else {
            cp_wait<0>();
        }
        __syncthreads();

        const float* At = AtB + (c % 3) * SA;
        const float* Vt = VtB + (c % 3) * SV;

        // write p = e * rinv back to attn
#pragma unroll
        for (int r = 0; r < 2; r++) {
            int idx = tid + 256 * r;
            int qi = idx >> 3, k4 = (idx & 7) * 4;
            float4 v = *(const float4*)&At[qi * 36 + k4];
            float riv = rs[qi];
            v.x *= riv; v.y *= riv; v.z *= riv; v.w *= riv;
            *(float4*)&attn[((size_t)bh * S_ + q0 + qi) * S_ + c * 32 + k4] = v;
        }

#pragma unroll
        for (int ds = 0; ds < 4; ds++) {
            FragA a;
            wmma::load_matrix_sync(a, &At[(wq * 16) * 36 + ds * 8], 36);
            cvt_tf32(a);
#pragma unroll
            for (int j = 0; j < 2; j++) {
                FragB bf;
                wmma::load_matrix_sync(bf, &Vt[ds * 8 * 68 + wd * 32 + j * 16], 68);
                cvt_tf32(bf);
                wmma::mma_sync(acc[j], a, bf, acc[j]);
            }
        }
        __syncthreads();
    }

    // epilogue: stage in smem, scale by rinv, store
#pragma unroll
    for (int j = 0; j < 2; j++)
        wmma::store_matrix_sync(&Cs[(wq * 16) * 68 + wd * 32 + j * 16],
                                acc[j], 68, wmma::mem_row_major);
    __syncthreads();

#pragma unroll
    for (int r = 0; r < 4; r++) {
        int idx = tid + 256 * r;
        int qi = idx >> 4, d4 = (idx & 15) * 4;
        float4 v = *(float4*)&Cs[qi * 68 + d4];
        float riv = rs[qi];
        v.x *= riv; v.y *= riv; v.z *= riv; v.w *= riv;
        *(float4*)&ctx[(size_t)(b * S_ + q0 + qi) * DA_ + h * DEP_ + d4] = v;
    }
}

// =================================================================
extern "C" void kernel_launch(void* const* d_in, const int* in_sizes, int n_in,
                              void* d_out, int out_size)
{
    const float* q     = (const float*)d_in[0];
    const float* k     = (const float*)d_in[1];
    const float* v     = (const float*)d_in[2];
    const float* xdiff = (const float*)d_in[3];
    const float* wq    = (const float*)d_in[4];
    const float* bq    = (const float*)d_in[5];
    const float* wk    = (const float*)d_in[6];
    const float* bk    = (const float*)d_in[7];
    const float* wv    = (const float*)d_in[8];
    const float* bv    = (const float*)d_in[9];
    const float* wx    = (const float*)d_in[10];
    const float* bx    = (const float*)d_in[11];
    const float* wo    = (const float*)d_in[12];
    const float* bo    = (const float*)d_in[13];

    float* out  = (float*)d_out;                        // [B,S,DM]
    float* attn = out + (size_t)BS_ * DM_;              // [B,H,S,S]

    float *qp, *kp, *vp, *xs, *ctx, *psum, *rinv;
    cudaGetSymbolAddress((void**)&qp,   g_qp);
    cudaGetSymbolAddress((void**)&kp,   g_kp);
    cudaGetSymbolAddress((void**)&vp,   g_vp);
    cudaGetSymbolAddress((void**)&xs,   g_xs);
    cudaGetSymbolAddress((void**)&ctx,  g_ctx);
    cudaGetSymbolAddress((void**)&psum, g_psum);
    cudaGetSymbolAddress((void**)&rinv, g_rinv);

    const int SM_G128 = (3 * 64 * 36 + 3 * 32 * 132) * 4;    // 78336
    const int SM_G32  = (3 * 64 * 36 + 3 * 32 * 36) * 4;     // 41472
    const int SM_LOG  = LOG_SMEM_BYTES;                      // 70656
    const int SM_PV   = PV_SMEM_BYTES;                       // 54016

    cudaFuncSetAttribute((const void*)gemm_wmma<64, 128, 2, 4>,
                         cudaFuncAttributeMaxDynamicSharedMemorySize, SM_G128);
    cudaFuncSetAttribute((const void*)gemm_wmma<64, 32, 4, 2>,
                         cudaFuncAttributeMaxDynamicSharedMemorySize, SM_G32);
    cudaFuncSetAttribute((const void*)logits_exp_wmma,
                         cudaFuncAttributeMaxDynamicSharedMemorySize, SM_LOG);
    cudaFuncSetAttribute((const void*)pv_wmma,
                         cudaFuncAttributeMaxDynamicSharedMemorySize, SM_PV);

    dim3 gProj(DA_ / 128, BS_ / 64);   // (4, 128)

    // projections (tf32 WMMA, 3-stage pipelined, 64-row tiles)
    gemm_wmma<64, 128, 2, 4><<<gProj, 256, SM_G128>>>(q, wq, bq, qp, BS_, DA_, DM_);
    gemm_wmma<64, 128, 2, 4><<<gProj, 256, SM_G128>>>(k, wk, bk, kp, BS_, DA_, DM_);
    gemm_wmma<64, 128, 2, 4><<<gProj, 256, SM_G128>>>(v, wv, bv, vp, BS_, DA_, DM_);

    // x = qp @ wx + bx
    gemm_wmma<64, 32, 4, 2><<<dim3(1, BS_ / 64), 256, SM_G32>>>(
        qp, wx, bx, xs, BS_, H_ * F_, DA_);

    // logits + bias + exp -> attn (unnormalized) + partial sums
    logits_exp_wmma<<<dim3(S_ / 32, S_ / 64, B_), 256, SM_LOG>>>(
        qp, kp, xs, xdiff, attn, psum);

    // rowsum -> 1/s
    rowsum_kernel<<<ROWS_ / 8, 256>>>(psum, rinv);

    // PV + in-place normalization of attn
    pv_wmma<<<dim3(S_ / 64, B_ * H_), 256, SM_PV>>>(attn, vp, rinv, ctx);

    // out = ctx @ wo + bo
    gemm_wmma<64, 128, 2, 4><<<dim3(DM_ / 128, BS_ / 64), 256, SM_G128>>>(
        ctx, wo, bo, out, BS_, DM_, DA_);
}